// round 8
// baseline (speedup 1.0000x reference)
#include <cuda_runtime.h>
#include <cstdint>
#include <cstddef>

// ============================================================================
// QuantumCoherentLayer — collapsed algebra (base sm_103: mma.sync tf32 + cp.async)
//
//   w[j]  = sum_i softmax_row_i(cos(phase * J_sym))[j]
//   alpha = clip(exp(-t/51), 0, 1)
//   W_eff = sum_j w[j] * W_paths[j];  M = W_input @ W_eff
//   out   = (a^2/64)*sum_j w[j]*coherent[:,j,:] + (a(1-a)/64)*(x @ M)
//
// R7: R6 showed 8-warp and 16-warp GEMM2 identical (47.5us) — time is split
// between a ~32us mainloop and a serialized ~15us epilogue tail that streams
// the 64MB coherent block from DRAM. Change: prefetch.global.L2 the CTA's
// 512KB coh slice during the first 8 k-iterations (8 lines/thread), so the
// epilogue hits L2 instead of DRAM.
// ============================================================================

#define PI_F 3.14159265358979323846f

static constexpr int H = 1024;
static constexpr int STAGES = 4;
static constexpr int KTILE = 32;
static constexpr int NKC = H / KTILE;   // 32

// ---------------- device scratch (no cudaMalloc allowed) ---------------------
__device__ float g_w[8];
__device__ float g_c[2];          // c1 = a^2/64, c2 = a(1-a)/64
__device__ float g_WeT[H * H];    // WeT[n][h] = W_eff[h][n]
__device__ float g_Mt[H * H];     // Mt[n][d]  = M[d][n]

// ---------------- asm helpers ------------------------------------------------
__device__ __forceinline__ uint32_t smem_u32(const void* p) {
    uint32_t a;
    asm("{ .reg .u64 t; cvta.to.shared.u64 t, %1; cvt.u32.u64 %0, t; }" : "=r"(a) : "l"(p));
    return a;
}
__device__ __forceinline__ void cp16(uint32_t s, const void* g) {
    asm volatile("cp.async.cg.shared.global [%0], [%1], 16;" :: "r"(s), "l"(g) : "memory");
}
#define CP_COMMIT() asm volatile("cp.async.commit_group;" ::: "memory")
#define CP_WAIT(n)  asm volatile("cp.async.wait_group %0;" :: "n"(n) : "memory")

__device__ __forceinline__ void l2_prefetch(const void* p) {
    asm volatile("prefetch.global.L2 [%0];" :: "l"(p));
}

__device__ __forceinline__ void mma8(float* d, const uint32_t* a, const uint32_t* b) {
    asm volatile(
        "mma.sync.aligned.m16n8k8.row.col.f32.tf32.tf32.f32 "
        "{%0,%1,%2,%3}, {%4,%5,%6,%7}, {%8,%9}, {%0,%1,%2,%3};"
        : "+f"(d[0]), "+f"(d[1]), "+f"(d[2]), "+f"(d[3])
        : "r"(a[0]), "r"(a[1]), "r"(a[2]), "r"(a[3]), "r"(b[0]), "r"(b[1]));
}

// ============================================================================
// Kernel 1: scalars
// ============================================================================
__global__ void k_scalars(const float* __restrict__ J, const float* __restrict__ t) {
    __shared__ float S[8][8];
    __shared__ float R[8][8];
    int tid = threadIdx.x;
    float tv = t[0];
    float phase = 2.0f * PI_F * 20.0f * tv / 1000.0f;
    if (tid < 64) {
        int i = tid >> 3, j = tid & 7;
        S[i][j] = cosf(phase * 0.5f * (J[i * 8 + j] + J[j * 8 + i]));
    }
    __syncthreads();
    if (tid < 8) {
        int i = tid;
        float mx = -1e30f;
        #pragma unroll
        for (int j = 0; j < 8; j++) mx = fmaxf(mx, S[i][j]);
        float e[8], s = 0.0f;
        #pragma unroll
        for (int j = 0; j < 8; j++) { e[j] = expf(S[i][j] - mx); s += e[j]; }
        float inv = 1.0f / s;
        #pragma unroll
        for (int j = 0; j < 8; j++) R[i][j] = e[j] * inv;
    }
    __syncthreads();
    if (tid < 8) {
        int j = tid;
        float w = 0.0f;
        #pragma unroll
        for (int i = 0; i < 8; i++) w += R[i][j];
        g_w[j] = w;
    }
    if (tid == 0) {
        float a = expf(-tv / 51.0f);
        a = fminf(fmaxf(a, 0.0f), 1.0f);
        g_c[0] = a * a / 64.0f;
        g_c[1] = a * (1.0f - a) / 64.0f;
    }
}

// ============================================================================
// Kernel 2: WeT[n][h] = sum_j w[j] * W_paths[j][h][n]  (weighted transpose)
// ============================================================================
__global__ void __launch_bounds__(256) k_wet(const float* __restrict__ Wp) {
    __shared__ float tile[32][133];
    float w[8];
    #pragma unroll
    for (int j = 0; j < 8; j++) w[j] = g_w[j];
    int h0 = blockIdx.x * 32, n0 = blockIdx.y * 128;
    int tid = threadIdx.x;

    #pragma unroll
    for (int i = tid; i < 32 * 32; i += 256) {
        int r = i >> 5, c4 = i & 31;
        const float* p = Wp + (size_t)(h0 + r) * H + n0 + c4 * 4;
        float4 acc = make_float4(0.f, 0.f, 0.f, 0.f);
        #pragma unroll
        for (int j = 0; j < 8; j++) {
            float4 v = *(const float4*)(p + (size_t)j * H * H);
            acc.x += w[j] * v.x; acc.y += w[j] * v.y;
            acc.z += w[j] * v.z; acc.w += w[j] * v.w;
        }
        tile[r][c4 * 4 + 0] = acc.x;
        tile[r][c4 * 4 + 1] = acc.y;
        tile[r][c4 * 4 + 2] = acc.z;
        tile[r][c4 * 4 + 3] = acc.w;
    }
    __syncthreads();
    #pragma unroll
    for (int i = tid; i < 128 * 32; i += 256) {
        int n = i >> 5, hc = i & 31;
        g_WeT[(size_t)(n0 + n) * H + h0 + hc] = tile[hc][n];
    }
}

// ============================================================================
// Tiled GEMM: C[i][j] = sum_k A[i][k]*B[j][k]  (A:[M,1024], B:[1024 rows,1024])
//   CTA tile BM x 128, warp tile 32x32, warp grid WGM x WGN, 4-stage cp.async.
//   k-slot remap: mma k-step (sp,u) slot c/h <-> k = 16sp+4c+2u+h (A/B agree).
//   SMEM [row][32k] f32 128B rows, chunk swizzle ch ^= 4*(row&1): LDS.128
//   conflict-free. Raw fp32 bits into HMMA (HW tf32 truncation).
//   EPI==1: prefetch coh slice to L2 during mainloop; epilogue
//           C = c2*C + c1*sum_j w[j]*coh[row][j][col] reads from L2.
// ============================================================================
template <int BM, int WGM, int WGN, int EPI>
__global__ void __launch_bounds__(WGM * WGN * 32, 1)
k_gemm(const float* __restrict__ A, const float* __restrict__ Bm,
       float* __restrict__ out, const float* __restrict__ coh) {
    constexpr int T = WGM * WGN * 32;
    constexpr int BN = 128;
    constexpr int ABYTES = BM * 128;
    constexpr int BBYTES = BN * 128;
    constexpr int STAGE_BYTES = ABYTES + BBYTES;

    extern __shared__ char smem[];
    uint32_t sbase = smem_u32(smem);

    int tid = threadIdx.x;
    int wid = tid >> 5, l = tid & 31;
    int wm = wid % WGM, wn = wid / WGM;
    int m0 = blockIdx.y * BM;
    int n0 = blockIdx.x * BN;
    int g = l >> 2, c = l & 3;
    int p4 = (g & 1) * 4;

    const float* gA = A + (size_t)m0 * H;
    const float* gB = Bm + (size_t)n0 * H;

    auto load_stage = [&](int kc, int stage) {
        uint32_t sA = sbase + stage * STAGE_BYTES;
        uint32_t sB = sA + ABYTES;
        const float* pA = gA + kc * KTILE;
        const float* pB = gB + kc * KTILE;
        #pragma unroll
        for (int i = tid; i < BM * 8; i += T) {
            int r = i >> 3, ch = i & 7;
            cp16(sA + r * 128 + ((ch ^ ((r & 1) * 4)) << 4), pA + (size_t)r * H + ch * 4);
        }
        #pragma unroll
        for (int i = tid; i < BN * 8; i += T) {
            int r = i >> 3, ch = i & 7;
            cp16(sB + r * 128 + ((ch ^ ((r & 1) * 4)) << 4), pB + (size_t)r * H + ch * 4);
        }
    };

    #pragma unroll
    for (int s = 0; s < STAGES - 1; s++) { load_stage(s, s); CP_COMMIT(); }

    float acc[2][4][4];
    #pragma unroll
    for (int mf = 0; mf < 2; mf++)
        #pragma unroll
        for (int f = 0; f < 4; f++)
            #pragma unroll
            for (int q = 0; q < 4; q++) acc[mf][f][q] = 0.0f;

    int rowA = wm * 32 + g;
    int rowB = wn * 32 + g;

    #pragma unroll 1
    for (int kc0 = 0; kc0 < NKC; kc0 += 4) {
        #pragma unroll
        for (int s4 = 0; s4 < 4; s4++) {
            int kc = kc0 + s4;
            CP_WAIT(STAGES - 2);
            __syncthreads();
            if (kc + STAGES - 1 < NKC) load_stage(kc + STAGES - 1, (kc + STAGES - 1) & 3);
            CP_COMMIT();

            // L2 prefetch of the CTA's coherent slice: 4096 lines over first 8
            // k-iters, one 128B line per thread per iter.
            if (EPI && kc < 4096 / T) {
                int idx = kc * T + tid;          // 0..4095
                int r = idx >> 5;                // 128 rows
                int j = (idx >> 2) & 7;          // 8 paths
                int q = idx & 3;                 // 4 lines per (row,path)
                l2_prefetch(coh + ((size_t)(m0 + r) * 8 + j) * H + n0 + q * 32);
            }

            const char* tA = smem + s4 * STAGE_BYTES;
            const char* tB = tA + ABYTES;

            #pragma unroll
            for (int sp = 0; sp < 2; sp++) {
                int ch = (4 * sp + c) ^ p4;
                uint4 av[4];
                #pragma unroll
                for (int rr = 0; rr < 4; rr++)
                    av[rr] = *(const uint4*)(tA + (rowA + rr * 8) * 128 + ch * 16);
                uint4 bv[4];
                #pragma unroll
                for (int f = 0; f < 4; f++)
                    bv[f] = *(const uint4*)(tB + (rowB + f * 8) * 128 + ch * 16);
                #pragma unroll
                for (int u = 0; u < 2; u++) {
                    #pragma unroll
                    for (int mf = 0; mf < 2; mf++) {
                        uint32_t a[4];
                        if (u == 0) {
                            a[0] = av[2 * mf].x; a[1] = av[2 * mf + 1].x;
                            a[2] = av[2 * mf].y; a[3] = av[2 * mf + 1].y;
                        } else {
                            a[0] = av[2 * mf].z; a[1] = av[2 * mf + 1].z;
                            a[2] = av[2 * mf].w; a[3] = av[2 * mf + 1].w;
                        }
                        #pragma unroll
                        for (int f = 0; f < 4; f++) {
                            uint32_t b[2];
                            if (u == 0) { b[0] = bv[f].x; b[1] = bv[f].y; }
                            else        { b[0] = bv[f].z; b[1] = bv[f].w; }
                            mma8(acc[mf][f], a, b);
                        }
                    }
                }
            }
        }
    }

    // ----------------- epilogue -----------------
    float c1 = 0.f, c2 = 0.f, w[8];
    if (EPI) {
        c1 = g_c[0]; c2 = g_c[1];
        #pragma unroll
        for (int j = 0; j < 8; j++) w[j] = g_w[j];
    }
    #pragma unroll
    for (int mf = 0; mf < 2; mf++) {
        #pragma unroll
        for (int hh = 0; hh < 2; hh++) {
            int row = m0 + wm * 32 + mf * 16 + hh * 8 + g;
            #pragma unroll
            for (int f = 0; f < 4; f++) {
                int col = n0 + wn * 32 + f * 8 + 2 * c;
                float v0 = acc[mf][f][2 * hh];
                float v1 = acc[mf][f][2 * hh + 1];
                if (EPI) {
                    float s0 = 0.f, s1 = 0.f;
                    const float* cp = coh + ((size_t)row * 8) * H + col;
                    #pragma unroll
                    for (int j = 0; j < 8; j++) {
                        float2 cv = *(const float2*)(cp + (size_t)j * H);
                        s0 += w[j] * cv.x;
                        s1 += w[j] * cv.y;
                    }
                    v0 = c2 * v0 + c1 * s0;
                    v1 = c2 * v1 + c1 * s1;
                }
                *(float2*)(out + (size_t)row * H + col) = make_float2(v0, v1);
            }
        }
    }
}

// ============================================================================
// Host side
// ============================================================================
extern "C" void kernel_launch(void* const* d_in, const int* in_sizes, int n_in,
                              void* d_out, int out_size) {
    const float* x   = (const float*)d_in[0];   // [2048, 1024]
    const float* Wi  = (const float*)d_in[1];   // [1024, 1024]
    const float* Wp  = (const float*)d_in[2];   // [8, 1024, 1024]
    const float* J   = (const float*)d_in[3];   // [8, 8]
    const float* coh = (const float*)d_in[4];   // [2048, 8, 1024]
    const float* t   = (const float*)d_in[5];   // [1]
    float* out = (float*)d_out;                 // [2048, 1024]
    (void)in_sizes; (void)n_in; (void)out_size;

    void* we_ptr = nullptr;
    void* mt_ptr = nullptr;
    cudaGetSymbolAddress(&we_ptr, g_WeT);
    cudaGetSymbolAddress(&mt_ptr, g_Mt);

    constexpr int SMEM1 = STAGES * (64 * 128 + 128 * 128);    // 96 KB
    constexpr int SMEM2 = STAGES * (128 * 128 + 128 * 128);   // 128 KB
    cudaFuncSetAttribute((const void*)k_gemm<64, 2, 4, 0>,
                         cudaFuncAttributeMaxDynamicSharedMemorySize, SMEM1);
    cudaFuncSetAttribute((const void*)k_gemm<128, 4, 4, 1>,
                         cudaFuncAttributeMaxDynamicSharedMemorySize, SMEM2);

    k_scalars<<<1, 64>>>(J, t);
    k_wet<<<dim3(32, 8), 256>>>(Wp);
    // GEMM1: Mt[n][d] = sum_h WeT[n][h] * Wi[d][h]
    k_gemm<64, 2, 4, 0><<<dim3(8, 16), 256, SMEM1>>>(
        (const float*)we_ptr, Wi, (float*)mt_ptr, nullptr);
    // GEMM2: out[b][n] = c2 * sum_d x[b][d]*Mt[n][d] + c1 * sum_j w[j]*coh[b][j][n]
    k_gemm<128, 4, 4, 1><<<dim3(8, 16), 512, SMEM2>>>(
        x, (const float*)mt_ptr, out, coh);
}

// round 9
// speedup vs baseline: 1.1934x; 1.1934x over previous
#include <cuda_runtime.h>
#include <cuda_bf16.h>
#include <cstdint>
#include <cstddef>

// ============================================================================
// QuantumCoherentLayer — collapsed algebra (base sm_103: mma.sync + cp.async)
//
//   w[j]  = sum_i softmax_row_i(cos(phase * J_sym))[j]
//   alpha = clip(exp(-t/51), 0, 1)
//   W_eff = sum_j w[j] * W_paths[j];  M = W_input @ W_eff
//   out   = (a^2/64)*sum_j w[j]*coherent[:,j,:] + (a(1-a)/64)*(x @ M)
//
// R8: evidence triangulated GEMM2's binder to the cp.async issue stream
// (warp count, smem traffic, ALU cuts all null/secondary; L2 prefetch hurt —
// reverted). Change: GEMM2 in bf16 (m16n8k16, KTILE=64) — halves cp.async
// count, LDS count, HMMA count, and smem traffic at once. x pre-converted to
// bf16 (k_xconv); GEMM1 stays tf32 but stores Mt as bf16. Error model: GEMM
// term is ~20% of output RMS -> predicted rel_err ~4-6e-4 (gate 1e-3).
// ============================================================================

#define PI_F 3.14159265358979323846f

static constexpr int H = 1024;
static constexpr int B = 2048;
static constexpr int STAGES = 4;

// ---------------- device scratch (no cudaMalloc allowed) ---------------------
__device__ float    g_w[8];
__device__ float    g_c[2];            // c1 = a^2/64, c2 = a(1-a)/64
__device__ float    g_WeT[H * H];      // WeT[n][h] = W_eff[h][n]  (fp32)
__device__ uint16_t g_Mtb[H * H];      // Mt[n][d] = M[d][n]       (bf16)
__device__ uint16_t g_xb[B * H];       // x in bf16

// ---------------- asm helpers ------------------------------------------------
__device__ __forceinline__ uint32_t smem_u32(const void* p) {
    uint32_t a;
    asm("{ .reg .u64 t; cvta.to.shared.u64 t, %1; cvt.u32.u64 %0, t; }" : "=r"(a) : "l"(p));
    return a;
}
__device__ __forceinline__ void cp16(uint32_t s, const void* g) {
    asm volatile("cp.async.cg.shared.global [%0], [%1], 16;" :: "r"(s), "l"(g) : "memory");
}
#define CP_COMMIT() asm volatile("cp.async.commit_group;" ::: "memory")
#define CP_WAIT(n)  asm volatile("cp.async.wait_group %0;" :: "n"(n) : "memory")

__device__ __forceinline__ void mma_tf32_8(float* d, const uint32_t* a, const uint32_t* b) {
    asm volatile(
        "mma.sync.aligned.m16n8k8.row.col.f32.tf32.tf32.f32 "
        "{%0,%1,%2,%3}, {%4,%5,%6,%7}, {%8,%9}, {%0,%1,%2,%3};"
        : "+f"(d[0]), "+f"(d[1]), "+f"(d[2]), "+f"(d[3])
        : "r"(a[0]), "r"(a[1]), "r"(a[2]), "r"(a[3]), "r"(b[0]), "r"(b[1]));
}
__device__ __forceinline__ void mma_bf16_16(float* d, const uint32_t* a, const uint32_t* b) {
    asm volatile(
        "mma.sync.aligned.m16n8k16.row.col.f32.bf16.bf16.f32 "
        "{%0,%1,%2,%3}, {%4,%5,%6,%7}, {%8,%9}, {%0,%1,%2,%3};"
        : "+f"(d[0]), "+f"(d[1]), "+f"(d[2]), "+f"(d[3])
        : "r"(a[0]), "r"(a[1]), "r"(a[2]), "r"(a[3]), "r"(b[0]), "r"(b[1]));
}

// ============================================================================
// Kernel 1: scalars
// ============================================================================
__global__ void k_scalars(const float* __restrict__ J, const float* __restrict__ t) {
    __shared__ float S[8][8];
    __shared__ float R[8][8];
    int tid = threadIdx.x;
    float tv = t[0];
    float phase = 2.0f * PI_F * 20.0f * tv / 1000.0f;
    if (tid < 64) {
        int i = tid >> 3, j = tid & 7;
        S[i][j] = cosf(phase * 0.5f * (J[i * 8 + j] + J[j * 8 + i]));
    }
    __syncthreads();
    if (tid < 8) {
        int i = tid;
        float mx = -1e30f;
        #pragma unroll
        for (int j = 0; j < 8; j++) mx = fmaxf(mx, S[i][j]);
        float e[8], s = 0.0f;
        #pragma unroll
        for (int j = 0; j < 8; j++) { e[j] = expf(S[i][j] - mx); s += e[j]; }
        float inv = 1.0f / s;
        #pragma unroll
        for (int j = 0; j < 8; j++) R[i][j] = e[j] * inv;
    }
    __syncthreads();
    if (tid < 8) {
        int j = tid;
        float w = 0.0f;
        #pragma unroll
        for (int i = 0; i < 8; i++) w += R[i][j];
        g_w[j] = w;
    }
    if (tid == 0) {
        float a = expf(-tv / 51.0f);
        a = fminf(fmaxf(a, 0.0f), 1.0f);
        g_c[0] = a * a / 64.0f;
        g_c[1] = a * (1.0f - a) / 64.0f;
    }
}

// ============================================================================
// Kernel: x -> bf16  (2M elements, float4 -> 4 bf16)
// ============================================================================
__global__ void __launch_bounds__(256) k_xconv(const float* __restrict__ x) {
    int idx = blockIdx.x * 256 + threadIdx.x;    // one float4 per thread
    float4 v = *(const float4*)(x + (size_t)idx * 4);
    __nv_bfloat162 lo = __float22bfloat162_rn(make_float2(v.x, v.y));
    __nv_bfloat162 hi = __float22bfloat162_rn(make_float2(v.z, v.w));
    uint2 pk;
    pk.x = *(uint32_t*)&lo;
    pk.y = *(uint32_t*)&hi;
    *(uint2*)(g_xb + (size_t)idx * 4) = pk;
}

// ============================================================================
// Kernel: WeT[n][h] = sum_j w[j] * W_paths[j][h][n]  (weighted transpose, fp32)
// ============================================================================
__global__ void __launch_bounds__(256) k_wet(const float* __restrict__ Wp) {
    __shared__ float tile[32][133];
    float w[8];
    #pragma unroll
    for (int j = 0; j < 8; j++) w[j] = g_w[j];
    int h0 = blockIdx.x * 32, n0 = blockIdx.y * 128;
    int tid = threadIdx.x;

    #pragma unroll
    for (int i = tid; i < 32 * 32; i += 256) {
        int r = i >> 5, c4 = i & 31;
        const float* p = Wp + (size_t)(h0 + r) * H + n0 + c4 * 4;
        float4 acc = make_float4(0.f, 0.f, 0.f, 0.f);
        #pragma unroll
        for (int j = 0; j < 8; j++) {
            float4 v = *(const float4*)(p + (size_t)j * H * H);
            acc.x += w[j] * v.x; acc.y += w[j] * v.y;
            acc.z += w[j] * v.z; acc.w += w[j] * v.w;
        }
        tile[r][c4 * 4 + 0] = acc.x;
        tile[r][c4 * 4 + 1] = acc.y;
        tile[r][c4 * 4 + 2] = acc.z;
        tile[r][c4 * 4 + 3] = acc.w;
    }
    __syncthreads();
    #pragma unroll
    for (int i = tid; i < 128 * 32; i += 256) {
        int n = i >> 5, hc = i & 31;
        g_WeT[(size_t)(n0 + n) * H + h0 + hc] = tile[hc][n];
    }
}

// ============================================================================
// GEMM1 (tf32): Mtb[n][d] = bf16( sum_h WeT[n][h] * Wi[d][h] )
//   CTA 64x128, 8 warps of 32x32, 4-stage cp.async, KTILE=32 f32 (128B rows),
//   chunk swizzle ch ^= 4*(row&1), raw fp32 bits into tf32 HMMA.
// ============================================================================
__global__ void __launch_bounds__(256, 1)
k_gemm1(const float* __restrict__ A, const float* __restrict__ Bm) {
    constexpr int BM = 64, BN = 128, T = 256;
    constexpr int NKC = 32;
    constexpr int ABYTES = BM * 128;
    constexpr int BBYTES = BN * 128;
    constexpr int STAGE_BYTES = ABYTES + BBYTES;

    extern __shared__ char smem[];
    uint32_t sbase = smem_u32(smem);

    int tid = threadIdx.x;
    int wid = tid >> 5, l = tid & 31;
    int wm = wid % 2, wn = wid / 2;
    int m0 = blockIdx.y * BM;
    int n0 = blockIdx.x * BN;
    int g = l >> 2, c = l & 3;
    int p4 = (g & 1) * 4;

    const float* gA = A + (size_t)m0 * H;
    const float* gB = Bm + (size_t)n0 * H;

    auto load_stage = [&](int kc, int stage) {
        uint32_t sA = sbase + stage * STAGE_BYTES;
        uint32_t sB = sA + ABYTES;
        const float* pA = gA + kc * 32;
        const float* pB = gB + kc * 32;
        #pragma unroll
        for (int i = tid; i < BM * 8; i += T) {
            int r = i >> 3, ch = i & 7;
            cp16(sA + r * 128 + ((ch ^ ((r & 1) * 4)) << 4), pA + (size_t)r * H + ch * 4);
        }
        #pragma unroll
        for (int i = tid; i < BN * 8; i += T) {
            int r = i >> 3, ch = i & 7;
            cp16(sB + r * 128 + ((ch ^ ((r & 1) * 4)) << 4), pB + (size_t)r * H + ch * 4);
        }
    };

    #pragma unroll
    for (int s = 0; s < STAGES - 1; s++) { load_stage(s, s); CP_COMMIT(); }

    float acc[2][4][4];
    #pragma unroll
    for (int mf = 0; mf < 2; mf++)
        #pragma unroll
        for (int f = 0; f < 4; f++)
            #pragma unroll
            for (int q = 0; q < 4; q++) acc[mf][f][q] = 0.0f;

    int rowA = wm * 32 + g;
    int rowB = wn * 32 + g;

    #pragma unroll 1
    for (int kc0 = 0; kc0 < NKC; kc0 += 4) {
        #pragma unroll
        for (int s4 = 0; s4 < 4; s4++) {
            int kc = kc0 + s4;
            CP_WAIT(STAGES - 2);
            __syncthreads();
            if (kc + STAGES - 1 < NKC) load_stage(kc + STAGES - 1, (kc + STAGES - 1) & 3);
            CP_COMMIT();

            const char* tA = smem + s4 * STAGE_BYTES;
            const char* tB = tA + ABYTES;

            #pragma unroll
            for (int sp = 0; sp < 2; sp++) {
                int ch = (4 * sp + c) ^ p4;
                uint4 av[4];
                #pragma unroll
                for (int rr = 0; rr < 4; rr++)
                    av[rr] = *(const uint4*)(tA + (rowA + rr * 8) * 128 + ch * 16);
                uint4 bv[4];
                #pragma unroll
                for (int f = 0; f < 4; f++)
                    bv[f] = *(const uint4*)(tB + (rowB + f * 8) * 128 + ch * 16);
                #pragma unroll
                for (int u = 0; u < 2; u++) {
                    #pragma unroll
                    for (int mf = 0; mf < 2; mf++) {
                        uint32_t a[4];
                        if (u == 0) {
                            a[0] = av[2 * mf].x; a[1] = av[2 * mf + 1].x;
                            a[2] = av[2 * mf].y; a[3] = av[2 * mf + 1].y;
                        } else {
                            a[0] = av[2 * mf].z; a[1] = av[2 * mf + 1].z;
                            a[2] = av[2 * mf].w; a[3] = av[2 * mf + 1].w;
                        }
                        #pragma unroll
                        for (int f = 0; f < 4; f++) {
                            uint32_t b[2];
                            if (u == 0) { b[0] = bv[f].x; b[1] = bv[f].y; }
                            else        { b[0] = bv[f].z; b[1] = bv[f].w; }
                            mma_tf32_8(acc[mf][f], a, b);
                        }
                    }
                }
            }
        }
    }

    // epilogue: store bf16 pairs into g_Mtb
    #pragma unroll
    for (int mf = 0; mf < 2; mf++) {
        #pragma unroll
        for (int hh = 0; hh < 2; hh++) {
            int row = m0 + wm * 32 + mf * 16 + hh * 8 + g;
            #pragma unroll
            for (int f = 0; f < 4; f++) {
                int col = n0 + wn * 32 + f * 8 + 2 * c;
                __nv_bfloat162 pv = __float22bfloat162_rn(
                    make_float2(acc[mf][f][2 * hh], acc[mf][f][2 * hh + 1]));
                *(uint32_t*)(g_Mtb + (size_t)row * H + col) = *(uint32_t*)&pv;
            }
        }
    }
}

// ============================================================================
// GEMM2 (bf16): out[b][n] = c2 * sum_d xb[b][d]*Mtb[n][d]
//                         + c1 * sum_j w[j]*coh[b][j][n]
//   CTA 128x128, 16 warps of 32x32, m16n8k16 bf16, KTILE=64 bf16 (128B rows),
//   4-stage cp.async, chunk swizzle ch ^= 4*(row&1).
//   k-remap: chunk (4h+c) low/high 8B = mma-steps (h,q); A/B agree per lane.
// ============================================================================
__global__ void __launch_bounds__(512, 1)
k_gemm2(const uint16_t* __restrict__ A, const uint16_t* __restrict__ Bm,
        float* __restrict__ out, const float* __restrict__ coh) {
    constexpr int BM = 128, BN = 128, T = 512;
    constexpr int NKC = 16;                  // 1024 / 64
    constexpr int ABYTES = BM * 128;         // 128 rows x 64 bf16
    constexpr int BBYTES = BN * 128;
    constexpr int STAGE_BYTES = ABYTES + BBYTES;   // 32 KB

    extern __shared__ char smem[];
    uint32_t sbase = smem_u32(smem);

    int tid = threadIdx.x;
    int wid = tid >> 5, l = tid & 31;
    int wm = wid % 4, wn = wid / 4;
    int m0 = blockIdx.y * BM;
    int n0 = blockIdx.x * BN;
    int g = l >> 2, c = l & 3;
    int p4 = (g & 1) * 4;

    const uint16_t* gA = A + (size_t)m0 * H;
    const uint16_t* gB = Bm + (size_t)n0 * H;

    auto load_stage = [&](int kc, int stage) {
        uint32_t sA = sbase + stage * STAGE_BYTES;
        uint32_t sB = sA + ABYTES;
        const uint16_t* pA = gA + kc * 64;
        const uint16_t* pB = gB + kc * 64;
        #pragma unroll
        for (int i = tid; i < BM * 8; i += T) {
            int r = i >> 3, ch = i & 7;
            cp16(sA + r * 128 + ((ch ^ ((r & 1) * 4)) << 4), pA + (size_t)r * H + ch * 8);
        }
        #pragma unroll
        for (int i = tid; i < BN * 8; i += T) {
            int r = i >> 3, ch = i & 7;
            cp16(sB + r * 128 + ((ch ^ ((r & 1) * 4)) << 4), pB + (size_t)r * H + ch * 8);
        }
    };

    #pragma unroll
    for (int s = 0; s < STAGES - 1; s++) { load_stage(s, s); CP_COMMIT(); }

    float acc[2][4][4];
    #pragma unroll
    for (int mf = 0; mf < 2; mf++)
        #pragma unroll
        for (int f = 0; f < 4; f++)
            #pragma unroll
            for (int q = 0; q < 4; q++) acc[mf][f][q] = 0.0f;

    int rowA = wm * 32 + g;
    int rowB = wn * 32 + g;

    #pragma unroll 1
    for (int kc0 = 0; kc0 < NKC; kc0 += 4) {
        #pragma unroll
        for (int s4 = 0; s4 < 4; s4++) {
            int kc = kc0 + s4;
            CP_WAIT(STAGES - 2);
            __syncthreads();
            if (kc + STAGES - 1 < NKC) load_stage(kc + STAGES - 1, (kc + STAGES - 1) & 3);
            CP_COMMIT();

            const char* tA = smem + s4 * STAGE_BYTES;
            const char* tB = tA + ABYTES;

            #pragma unroll
            for (int h = 0; h < 2; h++) {
                int ch = (4 * h + c) ^ p4;
                uint4 av[4];
                #pragma unroll
                for (int rr = 0; rr < 4; rr++)
                    av[rr] = *(const uint4*)(tA + (rowA + rr * 8) * 128 + ch * 16);
                uint4 bv[4];
                #pragma unroll
                for (int f = 0; f < 4; f++)
                    bv[f] = *(const uint4*)(tB + (rowB + f * 8) * 128 + ch * 16);
                #pragma unroll
                for (int q = 0; q < 2; q++) {
                    #pragma unroll
                    for (int mf = 0; mf < 2; mf++) {
                        uint32_t a[4];
                        if (q == 0) {
                            a[0] = av[2 * mf].x; a[1] = av[2 * mf + 1].x;
                            a[2] = av[2 * mf].y; a[3] = av[2 * mf + 1].y;
                        } else {
                            a[0] = av[2 * mf].z; a[1] = av[2 * mf + 1].z;
                            a[2] = av[2 * mf].w; a[3] = av[2 * mf + 1].w;
                        }
                        #pragma unroll
                        for (int f = 0; f < 4; f++) {
                            uint32_t b[2];
                            if (q == 0) { b[0] = bv[f].x; b[1] = bv[f].y; }
                            else        { b[0] = bv[f].z; b[1] = bv[f].w; }
                            mma_bf16_16(acc[mf][f], a, b);
                        }
                    }
                }
            }
        }
    }

    // ----------------- fused epilogue -----------------
    float c1 = g_c[0], c2 = g_c[1], w[8];
    #pragma unroll
    for (int j = 0; j < 8; j++) w[j] = g_w[j];
    #pragma unroll
    for (int mf = 0; mf < 2; mf++) {
        #pragma unroll
        for (int hh = 0; hh < 2; hh++) {
            int row = m0 + wm * 32 + mf * 16 + hh * 8 + g;
            #pragma unroll
            for (int f = 0; f < 4; f++) {
                int col = n0 + wn * 32 + f * 8 + 2 * c;
                float v0 = acc[mf][f][2 * hh];
                float v1 = acc[mf][f][2 * hh + 1];
                float s0 = 0.f, s1 = 0.f;
                const float* cp = coh + ((size_t)row * 8) * H + col;
                #pragma unroll
                for (int j = 0; j < 8; j++) {
                    float2 cv = *(const float2*)(cp + (size_t)j * H);
                    s0 += w[j] * cv.x;
                    s1 += w[j] * cv.y;
                }
                v0 = c2 * v0 + c1 * s0;
                v1 = c2 * v1 + c1 * s1;
                *(float2*)(out + (size_t)row * H + col) = make_float2(v0, v1);
            }
        }
    }
}

// ============================================================================
// Host side
// ============================================================================
extern "C" void kernel_launch(void* const* d_in, const int* in_sizes, int n_in,
                              void* d_out, int out_size) {
    const float* x   = (const float*)d_in[0];   // [2048, 1024]
    const float* Wi  = (const float*)d_in[1];   // [1024, 1024]
    const float* Wp  = (const float*)d_in[2];   // [8, 1024, 1024]
    const float* J   = (const float*)d_in[3];   // [8, 8]
    const float* coh = (const float*)d_in[4];   // [2048, 8, 1024]
    const float* t   = (const float*)d_in[5];   // [1]
    float* out = (float*)d_out;                 // [2048, 1024]
    (void)in_sizes; (void)n_in; (void)out_size;

    void* we_ptr = nullptr;
    void* mtb_ptr = nullptr;
    void* xb_ptr = nullptr;
    cudaGetSymbolAddress(&we_ptr, g_WeT);
    cudaGetSymbolAddress(&mtb_ptr, g_Mtb);
    cudaGetSymbolAddress(&xb_ptr, g_xb);

    constexpr int SMEM1 = STAGES * (64 * 128 + 128 * 128);    // 96 KB
    constexpr int SMEM2 = STAGES * (128 * 128 + 128 * 128);   // 128 KB
    cudaFuncSetAttribute((const void*)k_gemm1,
                         cudaFuncAttributeMaxDynamicSharedMemorySize, SMEM1);
    cudaFuncSetAttribute((const void*)k_gemm2,
                         cudaFuncAttributeMaxDynamicSharedMemorySize, SMEM2);

    k_scalars<<<1, 64>>>(J, t);
    k_xconv<<<(B * H / 4) / 256, 256>>>(x);
    k_wet<<<dim3(32, 8), 256>>>(Wp);
    // GEMM1: Mtb[n][d] = bf16( sum_h WeT[n][h] * Wi[d][h] )
    k_gemm1<<<dim3(8, 16), 256, SMEM1>>>((const float*)we_ptr, Wi);
    // GEMM2: out = c2 * xb@Mtb^T + c1 * coh-weighted-sum
    k_gemm2<<<dim3(8, 16), 512, SMEM2>>>(
        (const uint16_t*)xb_ptr, (const uint16_t*)mtb_ptr, out, coh);
}

// round 10
// speedup vs baseline: 1.4571x; 1.2210x over previous
#include <cuda_runtime.h>
#include <cuda_bf16.h>
#include <cstdint>
#include <cstddef>

// ============================================================================
// QuantumCoherentLayer — collapsed algebra (base sm_103: mma.sync + cp.async)
//
//   w[j]  = sum_i softmax_row_i(cos(phase * J_sym))[j]
//   alpha = clip(exp(-t/51), 0, 1)
//   W_eff = sum_j w[j] * W_paths[j];  M = W_input @ W_eff
//   out   = (a^2/64)*sum_j w[j]*coherent[:,j,:] + (a(1-a)/64)*(x @ M)
//
// R9 model: legacy HMMA issue floor (~8 cyc/SMSP/instr) binds both GEMMs;
// GEMM2's coh epilogue is a serialized DRAM tail. R10:
//  (1) GEMM1 in bf16 (m16n8k16) — halves its HMMA count + cp bytes.
//  (2) GEMM2 fuses the coh weighted sum INTO the mainloop accumulators:
//      x is pre-scaled by (1-a)/a at bf16-conversion, so
//      acc = (c2/c1)*gemm + sum_j w[j]*coh,  out = c1*acc.
//      Per ktile: 8 __ldcs float2 + 16 FFMA overlap the HMMA block.
// ============================================================================

#define PI_F 3.14159265358979323846f

static constexpr int H = 1024;
static constexpr int B = 2048;
static constexpr int STAGES = 4;

// ---------------- device scratch (no cudaMalloc allowed) ---------------------
__device__ float    g_w[8];
__device__ float    g_c[4];            // [0]=c1=a^2/64  [2]=(1-a)/a
__device__ uint16_t g_WeTb[H * H];     // WeT[n][h] = W_eff[h][n]  (bf16)
__device__ uint16_t g_Wib[H * H];      // W_input   (bf16, row-major [d][h])
__device__ uint16_t g_Mtb[H * H];      // Mt[n][d]  = M[d][n]      (bf16)
__device__ uint16_t g_xb[B * H];       // x * (1-a)/a              (bf16)

// ---------------- asm helpers ------------------------------------------------
__device__ __forceinline__ uint32_t smem_u32(const void* p) {
    uint32_t a;
    asm("{ .reg .u64 t; cvta.to.shared.u64 t, %1; cvt.u32.u64 %0, t; }" : "=r"(a) : "l"(p));
    return a;
}
__device__ __forceinline__ void cp16(uint32_t s, const void* g) {
    asm volatile("cp.async.cg.shared.global [%0], [%1], 16;" :: "r"(s), "l"(g) : "memory");
}
#define CP_COMMIT() asm volatile("cp.async.commit_group;" ::: "memory")
#define CP_WAIT(n)  asm volatile("cp.async.wait_group %0;" :: "n"(n) : "memory")

__device__ __forceinline__ void mma_bf16_16(float* d, const uint32_t* a, const uint32_t* b) {
    asm volatile(
        "mma.sync.aligned.m16n8k16.row.col.f32.bf16.bf16.f32 "
        "{%0,%1,%2,%3}, {%4,%5,%6,%7}, {%8,%9}, {%0,%1,%2,%3};"
        : "+f"(d[0]), "+f"(d[1]), "+f"(d[2]), "+f"(d[3])
        : "r"(a[0]), "r"(a[1]), "r"(a[2]), "r"(a[3]), "r"(b[0]), "r"(b[1]));
}

// ============================================================================
// Kernel 1: scalars
// ============================================================================
__global__ void k_scalars(const float* __restrict__ J, const float* __restrict__ t) {
    __shared__ float S[8][8];
    __shared__ float R[8][8];
    int tid = threadIdx.x;
    float tv = t[0];
    float phase = 2.0f * PI_F * 20.0f * tv / 1000.0f;
    if (tid < 64) {
        int i = tid >> 3, j = tid & 7;
        S[i][j] = cosf(phase * 0.5f * (J[i * 8 + j] + J[j * 8 + i]));
    }
    __syncthreads();
    if (tid < 8) {
        int i = tid;
        float mx = -1e30f;
        #pragma unroll
        for (int j = 0; j < 8; j++) mx = fmaxf(mx, S[i][j]);
        float e[8], s = 0.0f;
        #pragma unroll
        for (int j = 0; j < 8; j++) { e[j] = expf(S[i][j] - mx); s += e[j]; }
        float inv = 1.0f / s;
        #pragma unroll
        for (int j = 0; j < 8; j++) R[i][j] = e[j] * inv;
    }
    __syncthreads();
    if (tid < 8) {
        int j = tid;
        float w = 0.0f;
        #pragma unroll
        for (int i = 0; i < 8; i++) w += R[i][j];
        g_w[j] = w;
    }
    if (tid == 0) {
        float a = expf(-tv / 51.0f);
        a = fminf(fmaxf(a, 0.0f), 1.0f);
        g_c[0] = a * a / 64.0f;            // c1
        g_c[1] = a * (1.0f - a) / 64.0f;   // c2 (kept for reference)
        g_c[2] = (1.0f - a) / a;           // gemm pre-scale (finite: a in (0,1])
    }
}

// ============================================================================
// Conversions: x -> bf16 scaled by (1-a)/a;  Wi -> bf16 plain
// ============================================================================
__global__ void __launch_bounds__(256) k_xconv(const float* __restrict__ x) {
    float s = g_c[2];
    int idx = blockIdx.x * 256 + threadIdx.x;    // one float4 per thread
    float4 v = *(const float4*)(x + (size_t)idx * 4);
    __nv_bfloat162 lo = __float22bfloat162_rn(make_float2(v.x * s, v.y * s));
    __nv_bfloat162 hi = __float22bfloat162_rn(make_float2(v.z * s, v.w * s));
    uint2 pk;
    pk.x = *(uint32_t*)&lo;
    pk.y = *(uint32_t*)&hi;
    *(uint2*)(g_xb + (size_t)idx * 4) = pk;
}
__global__ void __launch_bounds__(256) k_wconv(const float* __restrict__ Wi) {
    int idx = blockIdx.x * 256 + threadIdx.x;
    float4 v = *(const float4*)(Wi + (size_t)idx * 4);
    __nv_bfloat162 lo = __float22bfloat162_rn(make_float2(v.x, v.y));
    __nv_bfloat162 hi = __float22bfloat162_rn(make_float2(v.z, v.w));
    uint2 pk;
    pk.x = *(uint32_t*)&lo;
    pk.y = *(uint32_t*)&hi;
    *(uint2*)(g_Wib + (size_t)idx * 4) = pk;
}

// ============================================================================
// k_wet: WeTb[n][h] = bf16( sum_j w[j] * W_paths[j][h][n] )
// ============================================================================
__global__ void __launch_bounds__(256) k_wet(const float* __restrict__ Wp) {
    __shared__ float tile[32][133];
    float w[8];
    #pragma unroll
    for (int j = 0; j < 8; j++) w[j] = g_w[j];
    int h0 = blockIdx.x * 32, n0 = blockIdx.y * 128;
    int tid = threadIdx.x;

    #pragma unroll
    for (int i = tid; i < 32 * 32; i += 256) {
        int r = i >> 5, c4 = i & 31;
        const float* p = Wp + (size_t)(h0 + r) * H + n0 + c4 * 4;
        float4 acc = make_float4(0.f, 0.f, 0.f, 0.f);
        #pragma unroll
        for (int j = 0; j < 8; j++) {
            float4 v = *(const float4*)(p + (size_t)j * H * H);
            acc.x += w[j] * v.x; acc.y += w[j] * v.y;
            acc.z += w[j] * v.z; acc.w += w[j] * v.w;
        }
        tile[r][c4 * 4 + 0] = acc.x;
        tile[r][c4 * 4 + 1] = acc.y;
        tile[r][c4 * 4 + 2] = acc.z;
        tile[r][c4 * 4 + 3] = acc.w;
    }
    __syncthreads();
    // transposed store as bf16 pairs: n-row, 16 h-pairs
    #pragma unroll
    for (int i = tid; i < 128 * 16; i += 256) {
        int n = i >> 4, hp = i & 15;
        __nv_bfloat162 pv = __float22bfloat162_rn(
            make_float2(tile[2 * hp][n], tile[2 * hp + 1][n]));
        *(uint32_t*)(g_WeTb + (size_t)(n0 + n) * H + h0 + 2 * hp) = *(uint32_t*)&pv;
    }
}

// ============================================================================
// GEMM1 (bf16): Mtb[n][d] = bf16( sum_h WeTb[n][h] * Wib[d][h] )
//   CTA 64x128, 8 warps of 32x32, m16n8k16, KTILE=64 bf16 (128B rows),
//   4-stage cp.async, chunk swizzle ch ^= 4*(row&1).
// ============================================================================
__global__ void __launch_bounds__(256, 1)
k_gemm1(const uint16_t* __restrict__ A, const uint16_t* __restrict__ Bm) {
    constexpr int BM = 64, BN = 128, T = 256;
    constexpr int NKC = 16;
    constexpr int ABYTES = BM * 128;
    constexpr int BBYTES = BN * 128;
    constexpr int STAGE_BYTES = ABYTES + BBYTES;

    extern __shared__ char smem[];
    uint32_t sbase = smem_u32(smem);

    int tid = threadIdx.x;
    int wid = tid >> 5, l = tid & 31;
    int wm = wid % 2, wn = wid / 2;
    int m0 = blockIdx.y * BM;
    int n0 = blockIdx.x * BN;
    int g = l >> 2, c = l & 3;
    int p4 = (g & 1) * 4;

    const uint16_t* gA = A + (size_t)m0 * H;
    const uint16_t* gB = Bm + (size_t)n0 * H;

    auto load_stage = [&](int kc, int stage) {
        uint32_t sA = sbase + stage * STAGE_BYTES;
        uint32_t sB = sA + ABYTES;
        const uint16_t* pA = gA + kc * 64;
        const uint16_t* pB = gB + kc * 64;
        #pragma unroll
        for (int i = tid; i < BM * 8; i += T) {
            int r = i >> 3, ch = i & 7;
            cp16(sA + r * 128 + ((ch ^ ((r & 1) * 4)) << 4), pA + (size_t)r * H + ch * 8);
        }
        #pragma unroll
        for (int i = tid; i < BN * 8; i += T) {
            int r = i >> 3, ch = i & 7;
            cp16(sB + r * 128 + ((ch ^ ((r & 1) * 4)) << 4), pB + (size_t)r * H + ch * 8);
        }
    };

    #pragma unroll
    for (int s = 0; s < STAGES - 1; s++) { load_stage(s, s); CP_COMMIT(); }

    float acc[2][4][4];
    #pragma unroll
    for (int mf = 0; mf < 2; mf++)
        #pragma unroll
        for (int f = 0; f < 4; f++)
            #pragma unroll
            for (int q = 0; q < 4; q++) acc[mf][f][q] = 0.0f;

    int rowA = wm * 32 + g;
    int rowB = wn * 32 + g;

    #pragma unroll 1
    for (int kc0 = 0; kc0 < NKC; kc0 += 4) {
        #pragma unroll
        for (int s4 = 0; s4 < 4; s4++) {
            int kc = kc0 + s4;
            CP_WAIT(STAGES - 2);
            __syncthreads();
            if (kc + STAGES - 1 < NKC) load_stage(kc + STAGES - 1, (kc + STAGES - 1) & 3);
            CP_COMMIT();

            const char* tA = smem + s4 * STAGE_BYTES;
            const char* tB = tA + ABYTES;

            #pragma unroll
            for (int hstep = 0; hstep < 2; hstep++) {
                int ch = (4 * hstep + c) ^ p4;
                uint4 av[4];
                #pragma unroll
                for (int rr = 0; rr < 4; rr++)
                    av[rr] = *(const uint4*)(tA + (rowA + rr * 8) * 128 + ch * 16);
                uint4 bv[4];
                #pragma unroll
                for (int f = 0; f < 4; f++)
                    bv[f] = *(const uint4*)(tB + (rowB + f * 8) * 128 + ch * 16);
                #pragma unroll
                for (int q = 0; q < 2; q++) {
                    #pragma unroll
                    for (int mf = 0; mf < 2; mf++) {
                        uint32_t a[4];
                        if (q == 0) {
                            a[0] = av[2 * mf].x; a[1] = av[2 * mf + 1].x;
                            a[2] = av[2 * mf].y; a[3] = av[2 * mf + 1].y;
                        } else {
                            a[0] = av[2 * mf].z; a[1] = av[2 * mf + 1].z;
                            a[2] = av[2 * mf].w; a[3] = av[2 * mf + 1].w;
                        }
                        #pragma unroll
                        for (int f = 0; f < 4; f++) {
                            uint32_t b[2];
                            if (q == 0) { b[0] = bv[f].x; b[1] = bv[f].y; }
                            else        { b[0] = bv[f].z; b[1] = bv[f].w; }
                            mma_bf16_16(acc[mf][f], a, b);
                        }
                    }
                }
            }
        }
    }

    #pragma unroll
    for (int mf = 0; mf < 2; mf++) {
        #pragma unroll
        for (int hh = 0; hh < 2; hh++) {
            int row = m0 + wm * 32 + mf * 16 + hh * 8 + g;
            #pragma unroll
            for (int f = 0; f < 4; f++) {
                int col = n0 + wn * 32 + f * 8 + 2 * c;
                __nv_bfloat162 pv = __float22bfloat162_rn(
                    make_float2(acc[mf][f][2 * hh], acc[mf][f][2 * hh + 1]));
                *(uint32_t*)(g_Mtb + (size_t)row * H + col) = *(uint32_t*)&pv;
            }
        }
    }
}

// ============================================================================
// GEMM2 (bf16 + fused coh): acc = xb@Mtb^T + sum_j w[j]*coh ; out = c1*acc
//   CTA 128x128, 16 warps of 32x32, m16n8k16, KTILE=64 bf16, 4-stage cp.async.
//   Per ktile kc: j=kc>>1, mf=kc&1 -> 8 __ldcs float2 of coh + 16 FFMA into acc,
//   overlapped with the HMMA block.
// ============================================================================
__global__ void __launch_bounds__(512, 1)
k_gemm2(const uint16_t* __restrict__ A, const uint16_t* __restrict__ Bm,
        float* __restrict__ out, const float* __restrict__ coh) {
    constexpr int BM = 128, BN = 128, T = 512;
    constexpr int NKC = 16;
    constexpr int ABYTES = BM * 128;
    constexpr int BBYTES = BN * 128;
    constexpr int STAGE_BYTES = ABYTES + BBYTES;

    extern __shared__ char smem[];
    uint32_t sbase = smem_u32(smem);

    int tid = threadIdx.x;
    int wid = tid >> 5, l = tid & 31;
    int wm = wid % 4, wn = wid / 4;
    int m0 = blockIdx.y * BM;
    int n0 = blockIdx.x * BN;
    int g = l >> 2, c = l & 3;
    int p4 = (g & 1) * 4;

    const uint16_t* gA = A + (size_t)m0 * H;
    const uint16_t* gB = Bm + (size_t)n0 * H;

    float w[8];
    #pragma unroll
    for (int j = 0; j < 8; j++) w[j] = g_w[j];

    // base pointer for this thread's coh columns (row part added per ktile)
    const float* cohbase = coh + n0 + wn * 32 + 2 * c;

    auto load_stage = [&](int kc, int stage) {
        uint32_t sA = sbase + stage * STAGE_BYTES;
        uint32_t sB = sA + ABYTES;
        const uint16_t* pA = gA + kc * 64;
        const uint16_t* pB = gB + kc * 64;
        #pragma unroll
        for (int i = tid; i < BM * 8; i += T) {
            int r = i >> 3, ch = i & 7;
            cp16(sA + r * 128 + ((ch ^ ((r & 1) * 4)) << 4), pA + (size_t)r * H + ch * 8);
        }
        #pragma unroll
        for (int i = tid; i < BN * 8; i += T) {
            int r = i >> 3, ch = i & 7;
            cp16(sB + r * 128 + ((ch ^ ((r & 1) * 4)) << 4), pB + (size_t)r * H + ch * 8);
        }
    };

    #pragma unroll
    for (int s = 0; s < STAGES - 1; s++) { load_stage(s, s); CP_COMMIT(); }

    float acc[2][4][4];
    #pragma unroll
    for (int mf = 0; mf < 2; mf++)
        #pragma unroll
        for (int f = 0; f < 4; f++)
            #pragma unroll
            for (int q = 0; q < 4; q++) acc[mf][f][q] = 0.0f;

    int rowA = wm * 32 + g;
    int rowB = wn * 32 + g;

    #pragma unroll 1
    for (int kc0 = 0; kc0 < NKC; kc0 += 4) {
        #pragma unroll
        for (int s4 = 0; s4 < 4; s4++) {
            int kc = kc0 + s4;
            CP_WAIT(STAGES - 2);
            __syncthreads();
            if (kc + STAGES - 1 < NKC) load_stage(kc + STAGES - 1, (kc + STAGES - 1) & 3);
            CP_COMMIT();

            // ---- issue coh loads for (j = kc>>1, mf = kc&1) ----
            int j = kc >> 1;
            int mfc = kc & 1;
            float2 ct[2][4];
            {
                #pragma unroll
                for (int hh = 0; hh < 2; hh++) {
                    int row = m0 + wm * 32 + mfc * 16 + hh * 8 + g;
                    const float* cp = cohbase + ((size_t)row * 8 + j) * H;
                    #pragma unroll
                    for (int f = 0; f < 4; f++)
                        ct[hh][f] = __ldcs((const float2*)(cp + f * 8));
                }
            }

            const char* tA = smem + s4 * STAGE_BYTES;
            const char* tB = tA + ABYTES;

            #pragma unroll
            for (int hstep = 0; hstep < 2; hstep++) {
                int ch = (4 * hstep + c) ^ p4;
                uint4 av[4];
                #pragma unroll
                for (int rr = 0; rr < 4; rr++)
                    av[rr] = *(const uint4*)(tA + (rowA + rr * 8) * 128 + ch * 16);
                uint4 bv[4];
                #pragma unroll
                for (int f = 0; f < 4; f++)
                    bv[f] = *(const uint4*)(tB + (rowB + f * 8) * 128 + ch * 16);
                #pragma unroll
                for (int q = 0; q < 2; q++) {
                    #pragma unroll
                    for (int mf = 0; mf < 2; mf++) {
                        uint32_t a[4];
                        if (q == 0) {
                            a[0] = av[2 * mf].x; a[1] = av[2 * mf + 1].x;
                            a[2] = av[2 * mf].y; a[3] = av[2 * mf + 1].y;
                        } else {
                            a[0] = av[2 * mf].z; a[1] = av[2 * mf + 1].z;
                            a[2] = av[2 * mf].w; a[3] = av[2 * mf + 1].w;
                        }
                        #pragma unroll
                        for (int f = 0; f < 4; f++) {
                            uint32_t b[2];
                            if (q == 0) { b[0] = bv[f].x; b[1] = bv[f].y; }
                            else        { b[0] = bv[f].z; b[1] = bv[f].w; }
                            mma_bf16_16(acc[mf][f], a, b);
                        }
                    }
                }
            }

            // ---- apply coh FMAs into acc (after HMMA block; loads have landed) ----
            float wj = w[j];
            #pragma unroll
            for (int hh = 0; hh < 2; hh++) {
                #pragma unroll
                for (int f = 0; f < 4; f++) {
                    acc[mfc][f][2 * hh]     += wj * ct[hh][f].x;
                    acc[mfc][f][2 * hh + 1] += wj * ct[hh][f].y;
                }
            }
        }
    }

    // ----------------- epilogue: out = c1 * acc -----------------
    float c1 = g_c[0];
    #pragma unroll
    for (int mf = 0; mf < 2; mf++) {
        #pragma unroll
        for (int hh = 0; hh < 2; hh++) {
            int row = m0 + wm * 32 + mf * 16 + hh * 8 + g;
            #pragma unroll
            for (int f = 0; f < 4; f++) {
                int col = n0 + wn * 32 + f * 8 + 2 * c;
                *(float2*)(out + (size_t)row * H + col) =
                    make_float2(c1 * acc[mf][f][2 * hh], c1 * acc[mf][f][2 * hh + 1]);
            }
        }
    }
}

// ============================================================================
// Host side
// ============================================================================
extern "C" void kernel_launch(void* const* d_in, const int* in_sizes, int n_in,
                              void* d_out, int out_size) {
    const float* x   = (const float*)d_in[0];   // [2048, 1024]
    const float* Wi  = (const float*)d_in[1];   // [1024, 1024]
    const float* Wp  = (const float*)d_in[2];   // [8, 1024, 1024]
    const float* J   = (const float*)d_in[3];   // [8, 8]
    const float* coh = (const float*)d_in[4];   // [2048, 8, 1024]
    const float* t   = (const float*)d_in[5];   // [1]
    float* out = (float*)d_out;                 // [2048, 1024]
    (void)in_sizes; (void)n_in; (void)out_size;

    void* wetb_ptr = nullptr;
    void* wib_ptr = nullptr;
    void* mtb_ptr = nullptr;
    void* xb_ptr = nullptr;
    cudaGetSymbolAddress(&wetb_ptr, g_WeTb);
    cudaGetSymbolAddress(&wib_ptr, g_Wib);
    cudaGetSymbolAddress(&mtb_ptr, g_Mtb);
    cudaGetSymbolAddress(&xb_ptr, g_xb);

    constexpr int SMEM1 = STAGES * (64 * 128 + 128 * 128);    // 96 KB
    constexpr int SMEM2 = STAGES * (128 * 128 + 128 * 128);   // 128 KB
    cudaFuncSetAttribute((const void*)k_gemm1,
                         cudaFuncAttributeMaxDynamicSharedMemorySize, SMEM1);
    cudaFuncSetAttribute((const void*)k_gemm2,
                         cudaFuncAttributeMaxDynamicSharedMemorySize, SMEM2);

    k_scalars<<<1, 64>>>(J, t);
    k_xconv<<<(B * H / 4) / 256, 256>>>(x);     // needs g_c[2] from k_scalars
    k_wconv<<<(H * H / 4) / 256, 256>>>(Wi);
    k_wet<<<dim3(32, 8), 256>>>(Wp);
    // GEMM1: Mtb[n][d] = bf16( sum_h WeTb[n][h] * Wib[d][h] )
    k_gemm1<<<dim3(8, 16), 256, SMEM1>>>(
        (const uint16_t*)wetb_ptr, (const uint16_t*)wib_ptr);
    // GEMM2: acc = xb@Mtb^T + sum_j w[j]*coh ; out = c1*acc
    k_gemm2<<<dim3(8, 16), 512, SMEM2>>>(
        (const uint16_t*)xb_ptr, (const uint16_t*)mtb_ptr, out, coh);
}

// round 11
// speedup vs baseline: 1.5067x; 1.0340x over previous
#include <cuda_runtime.h>
#include <cuda_bf16.h>
#include <cstdint>
#include <cstddef>

// ============================================================================
// QuantumCoherentLayer — collapsed algebra (base sm_103: mma.sync + cp.async)
//
//   w[j]  = sum_i softmax_row_i(cos(phase * J_sym))[j]
//   alpha = clip(exp(-t/51), 0, 1)
//   W_eff = sum_j w[j] * W_paths[j];  M = W_input @ W_eff
//   out   = (a^2/64)*sum_j w[j]*coherent[:,j,:] + (a(1-a)/64)*(x @ M)
//
// R11: k_wet was latency-exposed (issue 6.7%, 2.77TB/s, regs=32 -> no load
// batching). Changes (k_wet only): explicit 8-deep float4 load batching
// (MLP=8/thread) and 512-CTA grid (32h x 64n tiles). GEMMs unchanged from R10:
// bf16 m16n8k16, GEMM2 fuses coh stream into mainloop accumulators via
// x pre-scaled by (1-a)/a, out = c1*acc.
// ============================================================================

#define PI_F 3.14159265358979323846f

static constexpr int H = 1024;
static constexpr int B = 2048;
static constexpr int STAGES = 4;

// ---------------- device scratch (no cudaMalloc allowed) ---------------------
__device__ float    g_w[8];
__device__ float    g_c[4];            // [0]=c1=a^2/64  [2]=(1-a)/a
__device__ uint16_t g_WeTb[H * H];     // WeT[n][h] = W_eff[h][n]  (bf16)
__device__ uint16_t g_Wib[H * H];      // W_input   (bf16, row-major [d][h])
__device__ uint16_t g_Mtb[H * H];      // Mt[n][d]  = M[d][n]      (bf16)
__device__ uint16_t g_xb[B * H];       // x * (1-a)/a              (bf16)

// ---------------- asm helpers ------------------------------------------------
__device__ __forceinline__ uint32_t smem_u32(const void* p) {
    uint32_t a;
    asm("{ .reg .u64 t; cvta.to.shared.u64 t, %1; cvt.u32.u64 %0, t; }" : "=r"(a) : "l"(p));
    return a;
}
__device__ __forceinline__ void cp16(uint32_t s, const void* g) {
    asm volatile("cp.async.cg.shared.global [%0], [%1], 16;" :: "r"(s), "l"(g) : "memory");
}
#define CP_COMMIT() asm volatile("cp.async.commit_group;" ::: "memory")
#define CP_WAIT(n)  asm volatile("cp.async.wait_group %0;" :: "n"(n) : "memory")

__device__ __forceinline__ void mma_bf16_16(float* d, const uint32_t* a, const uint32_t* b) {
    asm volatile(
        "mma.sync.aligned.m16n8k16.row.col.f32.bf16.bf16.f32 "
        "{%0,%1,%2,%3}, {%4,%5,%6,%7}, {%8,%9}, {%0,%1,%2,%3};"
        : "+f"(d[0]), "+f"(d[1]), "+f"(d[2]), "+f"(d[3])
        : "r"(a[0]), "r"(a[1]), "r"(a[2]), "r"(a[3]), "r"(b[0]), "r"(b[1]));
}

// ============================================================================
// Kernel 1: scalars
// ============================================================================
__global__ void k_scalars(const float* __restrict__ J, const float* __restrict__ t) {
    __shared__ float S[8][8];
    __shared__ float R[8][8];
    int tid = threadIdx.x;
    float tv = t[0];
    float phase = 2.0f * PI_F * 20.0f * tv / 1000.0f;
    if (tid < 64) {
        int i = tid >> 3, j = tid & 7;
        S[i][j] = cosf(phase * 0.5f * (J[i * 8 + j] + J[j * 8 + i]));
    }
    __syncthreads();
    if (tid < 8) {
        int i = tid;
        float mx = -1e30f;
        #pragma unroll
        for (int j = 0; j < 8; j++) mx = fmaxf(mx, S[i][j]);
        float e[8], s = 0.0f;
        #pragma unroll
        for (int j = 0; j < 8; j++) { e[j] = expf(S[i][j] - mx); s += e[j]; }
        float inv = 1.0f / s;
        #pragma unroll
        for (int j = 0; j < 8; j++) R[i][j] = e[j] * inv;
    }
    __syncthreads();
    if (tid < 8) {
        int j = tid;
        float w = 0.0f;
        #pragma unroll
        for (int i = 0; i < 8; i++) w += R[i][j];
        g_w[j] = w;
    }
    if (tid == 0) {
        float a = expf(-tv / 51.0f);
        a = fminf(fmaxf(a, 0.0f), 1.0f);
        g_c[0] = a * a / 64.0f;            // c1
        g_c[1] = a * (1.0f - a) / 64.0f;   // c2 (reference)
        g_c[2] = (1.0f - a) / a;           // gemm pre-scale (finite: a in (0,1])
    }
}

// ============================================================================
// Conversions: x -> bf16 scaled by (1-a)/a;  Wi -> bf16 plain
// ============================================================================
__global__ void __launch_bounds__(256) k_xconv(const float* __restrict__ x) {
    float s = g_c[2];
    int idx = blockIdx.x * 256 + threadIdx.x;
    float4 v = *(const float4*)(x + (size_t)idx * 4);
    __nv_bfloat162 lo = __float22bfloat162_rn(make_float2(v.x * s, v.y * s));
    __nv_bfloat162 hi = __float22bfloat162_rn(make_float2(v.z * s, v.w * s));
    uint2 pk;
    pk.x = *(uint32_t*)&lo;
    pk.y = *(uint32_t*)&hi;
    *(uint2*)(g_xb + (size_t)idx * 4) = pk;
}
__global__ void __launch_bounds__(256) k_wconv(const float* __restrict__ Wi) {
    int idx = blockIdx.x * 256 + threadIdx.x;
    float4 v = *(const float4*)(Wi + (size_t)idx * 4);
    __nv_bfloat162 lo = __float22bfloat162_rn(make_float2(v.x, v.y));
    __nv_bfloat162 hi = __float22bfloat162_rn(make_float2(v.z, v.w));
    uint2 pk;
    pk.x = *(uint32_t*)&lo;
    pk.y = *(uint32_t*)&hi;
    *(uint2*)(g_Wib + (size_t)idx * 4) = pk;
}

// ============================================================================
// k_wet: WeTb[n][h] = bf16( sum_j w[j] * W_paths[j][h][n] )
//   Tile 32h x 64n, 512 CTAs, explicit 8-deep float4 load batching (MLP=8).
// ============================================================================
__global__ void __launch_bounds__(256) k_wet(const float* __restrict__ Wp) {
    __shared__ float tile[32][65];
    float w[8];
    #pragma unroll
    for (int j = 0; j < 8; j++) w[j] = g_w[j];
    int h0 = blockIdx.x * 32, n0 = blockIdx.y * 64;
    int tid = threadIdx.x;

    // load+weight: 32 rows x 16 float4-chunks, 2 iters/thread, 8 batched loads
    #pragma unroll
    for (int it = 0; it < 2; it++) {
        int i = it * 256 + tid;
        int r = i >> 4, c4 = i & 15;
        const float* p = Wp + (size_t)(h0 + r) * H + n0 + c4 * 4;
        float4 v[8];
        #pragma unroll
        for (int j = 0; j < 8; j++) v[j] = *(const float4*)(p + (size_t)j * H * H);
        float4 acc = make_float4(0.f, 0.f, 0.f, 0.f);
        #pragma unroll
        for (int j = 0; j < 8; j++) {
            acc.x += w[j] * v[j].x; acc.y += w[j] * v[j].y;
            acc.z += w[j] * v[j].z; acc.w += w[j] * v[j].w;
        }
        tile[r][c4 * 4 + 0] = acc.x;
        tile[r][c4 * 4 + 1] = acc.y;
        tile[r][c4 * 4 + 2] = acc.z;
        tile[r][c4 * 4 + 3] = acc.w;
    }
    __syncthreads();
    // transposed store as bf16 pairs: 64 n-rows x 16 h-pairs, 4 iters/thread
    #pragma unroll
    for (int it = 0; it < 4; it++) {
        int i = it * 256 + tid;
        int n = i >> 4, hp = i & 15;
        __nv_bfloat162 pv = __float22bfloat162_rn(
            make_float2(tile[2 * hp][n], tile[2 * hp + 1][n]));
        *(uint32_t*)(g_WeTb + (size_t)(n0 + n) * H + h0 + 2 * hp) = *(uint32_t*)&pv;
    }
}

// ============================================================================
// GEMM1 (bf16): Mtb[n][d] = bf16( sum_h WeTb[n][h] * Wib[d][h] )
//   CTA 64x128, 8 warps of 32x32, m16n8k16, KTILE=64 bf16, 4-stage cp.async.
// ============================================================================
__global__ void __launch_bounds__(256, 1)
k_gemm1(const uint16_t* __restrict__ A, const uint16_t* __restrict__ Bm) {
    constexpr int BM = 64, BN = 128, T = 256;
    constexpr int NKC = 16;
    constexpr int ABYTES = BM * 128;
    constexpr int BBYTES = BN * 128;
    constexpr int STAGE_BYTES = ABYTES + BBYTES;

    extern __shared__ char smem[];
    uint32_t sbase = smem_u32(smem);

    int tid = threadIdx.x;
    int wid = tid >> 5, l = tid & 31;
    int wm = wid % 2, wn = wid / 2;
    int m0 = blockIdx.y * BM;
    int n0 = blockIdx.x * BN;
    int g = l >> 2, c = l & 3;
    int p4 = (g & 1) * 4;

    const uint16_t* gA = A + (size_t)m0 * H;
    const uint16_t* gB = Bm + (size_t)n0 * H;

    auto load_stage = [&](int kc, int stage) {
        uint32_t sA = sbase + stage * STAGE_BYTES;
        uint32_t sB = sA + ABYTES;
        const uint16_t* pA = gA + kc * 64;
        const uint16_t* pB = gB + kc * 64;
        #pragma unroll
        for (int i = tid; i < BM * 8; i += T) {
            int r = i >> 3, ch = i & 7;
            cp16(sA + r * 128 + ((ch ^ ((r & 1) * 4)) << 4), pA + (size_t)r * H + ch * 8);
        }
        #pragma unroll
        for (int i = tid; i < BN * 8; i += T) {
            int r = i >> 3, ch = i & 7;
            cp16(sB + r * 128 + ((ch ^ ((r & 1) * 4)) << 4), pB + (size_t)r * H + ch * 8);
        }
    };

    #pragma unroll
    for (int s = 0; s < STAGES - 1; s++) { load_stage(s, s); CP_COMMIT(); }

    float acc[2][4][4];
    #pragma unroll
    for (int mf = 0; mf < 2; mf++)
        #pragma unroll
        for (int f = 0; f < 4; f++)
            #pragma unroll
            for (int q = 0; q < 4; q++) acc[mf][f][q] = 0.0f;

    int rowA = wm * 32 + g;
    int rowB = wn * 32 + g;

    #pragma unroll 1
    for (int kc0 = 0; kc0 < NKC; kc0 += 4) {
        #pragma unroll
        for (int s4 = 0; s4 < 4; s4++) {
            int kc = kc0 + s4;
            CP_WAIT(STAGES - 2);
            __syncthreads();
            if (kc + STAGES - 1 < NKC) load_stage(kc + STAGES - 1, (kc + STAGES - 1) & 3);
            CP_COMMIT();

            const char* tA = smem + s4 * STAGE_BYTES;
            const char* tB = tA + ABYTES;

            #pragma unroll
            for (int hstep = 0; hstep < 2; hstep++) {
                int ch = (4 * hstep + c) ^ p4;
                uint4 av[4];
                #pragma unroll
                for (int rr = 0; rr < 4; rr++)
                    av[rr] = *(const uint4*)(tA + (rowA + rr * 8) * 128 + ch * 16);
                uint4 bv[4];
                #pragma unroll
                for (int f = 0; f < 4; f++)
                    bv[f] = *(const uint4*)(tB + (rowB + f * 8) * 128 + ch * 16);
                #pragma unroll
                for (int q = 0; q < 2; q++) {
                    #pragma unroll
                    for (int mf = 0; mf < 2; mf++) {
                        uint32_t a[4];
                        if (q == 0) {
                            a[0] = av[2 * mf].x; a[1] = av[2 * mf + 1].x;
                            a[2] = av[2 * mf].y; a[3] = av[2 * mf + 1].y;
                        } else {
                            a[0] = av[2 * mf].z; a[1] = av[2 * mf + 1].z;
                            a[2] = av[2 * mf].w; a[3] = av[2 * mf + 1].w;
                        }
                        #pragma unroll
                        for (int f = 0; f < 4; f++) {
                            uint32_t b[2];
                            if (q == 0) { b[0] = bv[f].x; b[1] = bv[f].y; }
                            else        { b[0] = bv[f].z; b[1] = bv[f].w; }
                            mma_bf16_16(acc[mf][f], a, b);
                        }
                    }
                }
            }
        }
    }

    #pragma unroll
    for (int mf = 0; mf < 2; mf++) {
        #pragma unroll
        for (int hh = 0; hh < 2; hh++) {
            int row = m0 + wm * 32 + mf * 16 + hh * 8 + g;
            #pragma unroll
            for (int f = 0; f < 4; f++) {
                int col = n0 + wn * 32 + f * 8 + 2 * c;
                __nv_bfloat162 pv = __float22bfloat162_rn(
                    make_float2(acc[mf][f][2 * hh], acc[mf][f][2 * hh + 1]));
                *(uint32_t*)(g_Mtb + (size_t)row * H + col) = *(uint32_t*)&pv;
            }
        }
    }
}

// ============================================================================
// GEMM2 (bf16 + fused coh): acc = xb@Mtb^T + sum_j w[j]*coh ; out = c1*acc
//   CTA 128x128, 16 warps of 32x32, m16n8k16, KTILE=64 bf16, 4-stage cp.async.
//   Per ktile kc: j=kc>>1, mf=kc&1 -> 8 __ldcs float2 of coh + 16 FFMA into acc.
// ============================================================================
__global__ void __launch_bounds__(512, 1)
k_gemm2(const uint16_t* __restrict__ A, const uint16_t* __restrict__ Bm,
        float* __restrict__ out, const float* __restrict__ coh) {
    constexpr int BM = 128, BN = 128, T = 512;
    constexpr int NKC = 16;
    constexpr int ABYTES = BM * 128;
    constexpr int BBYTES = BN * 128;
    constexpr int STAGE_BYTES = ABYTES + BBYTES;

    extern __shared__ char smem[];
    uint32_t sbase = smem_u32(smem);

    int tid = threadIdx.x;
    int wid = tid >> 5, l = tid & 31;
    int wm = wid % 4, wn = wid / 4;
    int m0 = blockIdx.y * BM;
    int n0 = blockIdx.x * BN;
    int g = l >> 2, c = l & 3;
    int p4 = (g & 1) * 4;

    const uint16_t* gA = A + (size_t)m0 * H;
    const uint16_t* gB = Bm + (size_t)n0 * H;

    float w[8];
    #pragma unroll
    for (int j = 0; j < 8; j++) w[j] = g_w[j];

    const float* cohbase = coh + n0 + wn * 32 + 2 * c;

    auto load_stage = [&](int kc, int stage) {
        uint32_t sA = sbase + stage * STAGE_BYTES;
        uint32_t sB = sA + ABYTES;
        const uint16_t* pA = gA + kc * 64;
        const uint16_t* pB = gB + kc * 64;
        #pragma unroll
        for (int i = tid; i < BM * 8; i += T) {
            int r = i >> 3, ch = i & 7;
            cp16(sA + r * 128 + ((ch ^ ((r & 1) * 4)) << 4), pA + (size_t)r * H + ch * 8);
        }
        #pragma unroll
        for (int i = tid; i < BN * 8; i += T) {
            int r = i >> 3, ch = i & 7;
            cp16(sB + r * 128 + ((ch ^ ((r & 1) * 4)) << 4), pB + (size_t)r * H + ch * 8);
        }
    };

    #pragma unroll
    for (int s = 0; s < STAGES - 1; s++) { load_stage(s, s); CP_COMMIT(); }

    float acc[2][4][4];
    #pragma unroll
    for (int mf = 0; mf < 2; mf++)
        #pragma unroll
        for (int f = 0; f < 4; f++)
            #pragma unroll
            for (int q = 0; q < 4; q++) acc[mf][f][q] = 0.0f;

    int rowA = wm * 32 + g;
    int rowB = wn * 32 + g;

    #pragma unroll 1
    for (int kc0 = 0; kc0 < NKC; kc0 += 4) {
        #pragma unroll
        for (int s4 = 0; s4 < 4; s4++) {
            int kc = kc0 + s4;
            CP_WAIT(STAGES - 2);
            __syncthreads();
            if (kc + STAGES - 1 < NKC) load_stage(kc + STAGES - 1, (kc + STAGES - 1) & 3);
            CP_COMMIT();

            // ---- coh loads for (j = kc>>1, mf = kc&1) ----
            int j = kc >> 1;
            int mfc = kc & 1;
            float2 ct[2][4];
            {
                #pragma unroll
                for (int hh = 0; hh < 2; hh++) {
                    int row = m0 + wm * 32 + mfc * 16 + hh * 8 + g;
                    const float* cp = cohbase + ((size_t)row * 8 + j) * H;
                    #pragma unroll
                    for (int f = 0; f < 4; f++)
                        ct[hh][f] = __ldcs((const float2*)(cp + f * 8));
                }
            }

            const char* tA = smem + s4 * STAGE_BYTES;
            const char* tB = tA + ABYTES;

            #pragma unroll
            for (int hstep = 0; hstep < 2; hstep++) {
                int ch = (4 * hstep + c) ^ p4;
                uint4 av[4];
                #pragma unroll
                for (int rr = 0; rr < 4; rr++)
                    av[rr] = *(const uint4*)(tA + (rowA + rr * 8) * 128 + ch * 16);
                uint4 bv[4];
                #pragma unroll
                for (int f = 0; f < 4; f++)
                    bv[f] = *(const uint4*)(tB + (rowB + f * 8) * 128 + ch * 16);
                #pragma unroll
                for (int q = 0; q < 2; q++) {
                    #pragma unroll
                    for (int mf = 0; mf < 2; mf++) {
                        uint32_t a[4];
                        if (q == 0) {
                            a[0] = av[2 * mf].x; a[1] = av[2 * mf + 1].x;
                            a[2] = av[2 * mf].y; a[3] = av[2 * mf + 1].y;
                        } else {
                            a[0] = av[2 * mf].z; a[1] = av[2 * mf + 1].z;
                            a[2] = av[2 * mf].w; a[3] = av[2 * mf + 1].w;
                        }
                        #pragma unroll
                        for (int f = 0; f < 4; f++) {
                            uint32_t b[2];
                            if (q == 0) { b[0] = bv[f].x; b[1] = bv[f].y; }
                            else        { b[0] = bv[f].z; b[1] = bv[f].w; }
                            mma_bf16_16(acc[mf][f], a, b);
                        }
                    }
                }
            }

            // ---- apply coh FMAs into acc ----
            float wj = w[j];
            #pragma unroll
            for (int hh = 0; hh < 2; hh++) {
                #pragma unroll
                for (int f = 0; f < 4; f++) {
                    acc[mfc][f][2 * hh]     += wj * ct[hh][f].x;
                    acc[mfc][f][2 * hh + 1] += wj * ct[hh][f].y;
                }
            }
        }
    }

    // ----------------- epilogue: out = c1 * acc -----------------
    float c1 = g_c[0];
    #pragma unroll
    for (int mf = 0; mf < 2; mf++) {
        #pragma unroll
        for (int hh = 0; hh < 2; hh++) {
            int row = m0 + wm * 32 + mf * 16 + hh * 8 + g;
            #pragma unroll
            for (int f = 0; f < 4; f++) {
                int col = n0 + wn * 32 + f * 8 + 2 * c;
                *(float2*)(out + (size_t)row * H + col) =
                    make_float2(c1 * acc[mf][f][2 * hh], c1 * acc[mf][f][2 * hh + 1]);
            }
        }
    }
}

// ============================================================================
// Host side
// ============================================================================
extern "C" void kernel_launch(void* const* d_in, const int* in_sizes, int n_in,
                              void* d_out, int out_size) {
    const float* x   = (const float*)d_in[0];   // [2048, 1024]
    const float* Wi  = (const float*)d_in[1];   // [1024, 1024]
    const float* Wp  = (const float*)d_in[2];   // [8, 1024, 1024]
    const float* J   = (const float*)d_in[3];   // [8, 8]
    const float* coh = (const float*)d_in[4];   // [2048, 8, 1024]
    const float* t   = (const float*)d_in[5];   // [1]
    float* out = (float*)d_out;                 // [2048, 1024]
    (void)in_sizes; (void)n_in; (void)out_size;

    void* wetb_ptr = nullptr;
    void* wib_ptr = nullptr;
    void* mtb_ptr = nullptr;
    void* xb_ptr = nullptr;
    cudaGetSymbolAddress(&wetb_ptr, g_WeTb);
    cudaGetSymbolAddress(&wib_ptr, g_Wib);
    cudaGetSymbolAddress(&mtb_ptr, g_Mtb);
    cudaGetSymbolAddress(&xb_ptr, g_xb);

    constexpr int SMEM1 = STAGES * (64 * 128 + 128 * 128);    // 96 KB
    constexpr int SMEM2 = STAGES * (128 * 128 + 128 * 128);   // 128 KB
    cudaFuncSetAttribute((const void*)k_gemm1,
                         cudaFuncAttributeMaxDynamicSharedMemorySize, SMEM1);
    cudaFuncSetAttribute((const void*)k_gemm2,
                         cudaFuncAttributeMaxDynamicSharedMemorySize, SMEM2);

    k_scalars<<<1, 64>>>(J, t);
    k_xconv<<<(B * H / 4) / 256, 256>>>(x);     // needs g_c[2] from k_scalars
    k_wconv<<<(H * H / 4) / 256, 256>>>(Wi);
    k_wet<<<dim3(32, 16), 256>>>(Wp);
    // GEMM1: Mtb[n][d] = bf16( sum_h WeTb[n][h] * Wib[d][h] )
    k_gemm1<<<dim3(8, 16), 256, SMEM1>>>(
        (const uint16_t*)wetb_ptr, (const uint16_t*)wib_ptr);
    // GEMM2: acc = xb@Mtb^T + sum_j w[j]*coh ; out = c1*acc
    k_gemm2<<<dim3(8, 16), 512, SMEM2>>>(
        (const uint16_t*)xb_ptr, (const uint16_t*)mtb_ptr, out, coh);
}

// round 13
// speedup vs baseline: 1.5508x; 1.0293x over previous
#include <cuda_runtime.h>
#include <cuda_bf16.h>
#include <cstdint>
#include <cstddef>

// ============================================================================
// QuantumCoherentLayer — collapsed algebra (base sm_103: mma.sync + cp.async)
//
//   w[j]  = sum_i softmax_row_i(cos(phase * J_sym))[j]
//   alpha = clip(exp(-t/51), 0, 1)
//   W_eff = sum_j w[j] * W_paths[j];  M = W_input @ W_eff
//   out   = (a^2/64)*sum_j w[j]*coherent[:,j,:] + (a(1-a)/64)*(x @ M)
//
// R12 (resubmit after infra failure): force k_wet MLP=16 with volatile
// inline-asm ld.global.nc.v4.f32 (16 back-to-back loads, results all live);
// merged xconv+wconv into one launch. GEMMs unchanged (bf16 m16n8k16,
// GEMM2 fuses coh into mainloop accumulators; out = c1*acc).
// ============================================================================

#define PI_F 3.14159265358979323846f

static constexpr int H = 1024;
static constexpr int B = 2048;
static constexpr int STAGES = 4;

// ---------------- device scratch (no cudaMalloc allowed) ---------------------
__device__ float    g_w[8];
__device__ float    g_c[4];            // [0]=c1=a^2/64  [2]=(1-a)/a
__device__ uint16_t g_WeTb[H * H];     // WeT[n][h] = W_eff[h][n]  (bf16)
__device__ uint16_t g_Wib[H * H];      // W_input   (bf16, row-major [d][h])
__device__ uint16_t g_Mtb[H * H];      // Mt[n][d]  = M[d][n]      (bf16)
__device__ uint16_t g_xb[B * H];       // x * (1-a)/a              (bf16)

// ---------------- asm helpers ------------------------------------------------
__device__ __forceinline__ uint32_t smem_u32(const void* p) {
    uint32_t a;
    asm("{ .reg .u64 t; cvta.to.shared.u64 t, %1; cvt.u32.u64 %0, t; }" : "=r"(a) : "l"(p));
    return a;
}
__device__ __forceinline__ void cp16(uint32_t s, const void* g) {
    asm volatile("cp.async.cg.shared.global [%0], [%1], 16;" :: "r"(s), "l"(g) : "memory");
}
#define CP_COMMIT() asm volatile("cp.async.commit_group;" ::: "memory")
#define CP_WAIT(n)  asm volatile("cp.async.wait_group %0;" :: "n"(n) : "memory")

// volatile: ptxas may not reorder/coalesce these -> forced back-to-back LDGs
__device__ __forceinline__ float4 ldg_v4_nc(const float* p) {
    float4 v;
    asm volatile("ld.global.nc.v4.f32 {%0,%1,%2,%3}, [%4];"
                 : "=f"(v.x), "=f"(v.y), "=f"(v.z), "=f"(v.w) : "l"(p));
    return v;
}

__device__ __forceinline__ void mma_bf16_16(float* d, const uint32_t* a, const uint32_t* b) {
    asm volatile(
        "mma.sync.aligned.m16n8k16.row.col.f32.bf16.bf16.f32 "
        "{%0,%1,%2,%3}, {%4,%5,%6,%7}, {%8,%9}, {%0,%1,%2,%3};"
        : "+f"(d[0]), "+f"(d[1]), "+f"(d[2]), "+f"(d[3])
        : "r"(a[0]), "r"(a[1]), "r"(a[2]), "r"(a[3]), "r"(b[0]), "r"(b[1]));
}

// ============================================================================
// Kernel 1: scalars
// ============================================================================
__global__ void k_scalars(const float* __restrict__ J, const float* __restrict__ t) {
    __shared__ float S[8][8];
    __shared__ float R[8][8];
    int tid = threadIdx.x;
    float tv = t[0];
    float phase = 2.0f * PI_F * 20.0f * tv / 1000.0f;
    if (tid < 64) {
        int i = tid >> 3, j = tid & 7;
        S[i][j] = cosf(phase * 0.5f * (J[i * 8 + j] + J[j * 8 + i]));
    }
    __syncthreads();
    if (tid < 8) {
        int i = tid;
        float mx = -1e30f;
        #pragma unroll
        for (int j = 0; j < 8; j++) mx = fmaxf(mx, S[i][j]);
        float e[8], s = 0.0f;
        #pragma unroll
        for (int j = 0; j < 8; j++) { e[j] = expf(S[i][j] - mx); s += e[j]; }
        float inv = 1.0f / s;
        #pragma unroll
        for (int j = 0; j < 8; j++) R[i][j] = e[j] * inv;
    }
    __syncthreads();
    if (tid < 8) {
        int j = tid;
        float w = 0.0f;
        #pragma unroll
        for (int i = 0; i < 8; i++) w += R[i][j];
        g_w[j] = w;
    }
    if (tid == 0) {
        float a = expf(-tv / 51.0f);
        a = fminf(fmaxf(a, 0.0f), 1.0f);
        g_c[0] = a * a / 64.0f;            // c1
        g_c[1] = a * (1.0f - a) / 64.0f;   // c2 (reference)
        g_c[2] = (1.0f - a) / a;           // gemm pre-scale (finite: a in (0,1])
    }
}

// ============================================================================
// k_conv: merged  xb = bf16(x*(1-a)/a)  and  Wib = bf16(Wi)
//   blocks [0, NXB)   -> x part
//   blocks [NXB, end) -> Wi part
// ============================================================================
static constexpr int NXB = (B * H / 4) / 256;        // 2048 blocks
static constexpr int NWB = (H * H / 4) / 256;        // 1024 blocks

__global__ void __launch_bounds__(256) k_conv(const float* __restrict__ x,
                                              const float* __restrict__ Wi) {
    int bid = blockIdx.x;
    if (bid < NXB) {
        float s = g_c[2];
        int idx = bid * 256 + threadIdx.x;
        float4 v = *(const float4*)(x + (size_t)idx * 4);
        __nv_bfloat162 lo = __float22bfloat162_rn(make_float2(v.x * s, v.y * s));
        __nv_bfloat162 hi = __float22bfloat162_rn(make_float2(v.z * s, v.w * s));
        uint2 pk;
        pk.x = *(uint32_t*)&lo;
        pk.y = *(uint32_t*)&hi;
        *(uint2*)(g_xb + (size_t)idx * 4) = pk;
    } else {
        int idx = (bid - NXB) * 256 + threadIdx.x;
        float4 v = *(const float4*)(Wi + (size_t)idx * 4);
        __nv_bfloat162 lo = __float22bfloat162_rn(make_float2(v.x, v.y));
        __nv_bfloat162 hi = __float22bfloat162_rn(make_float2(v.z, v.w));
        uint2 pk;
        pk.x = *(uint32_t*)&lo;
        pk.y = *(uint32_t*)&hi;
        *(uint2*)(g_Wib + (size_t)idx * 4) = pk;
    }
}

// ============================================================================
// k_wet: WeTb[n][h] = bf16( sum_j w[j] * W_paths[j][h][n] )
//   Tile 32h x 64n, 512 CTAs. 16 volatile ld.global.nc.v4 issued back-to-back
//   (both row-iters x 8 paths) before any FMA -> forced MLP=16/thread.
// ============================================================================
__global__ void __launch_bounds__(256) k_wet(const float* __restrict__ Wp) {
    __shared__ float tile[32][65];
    float w[8];
    #pragma unroll
    for (int j = 0; j < 8; j++) w[j] = g_w[j];
    int h0 = blockIdx.x * 32, n0 = blockIdx.y * 64;
    int tid = threadIdx.x;

    // two (row, chunk) positions per thread
    int i0 = tid, i1 = 256 + tid;
    int r0 = i0 >> 4, c0 = i0 & 15;
    int r1 = i1 >> 4, c1 = i1 & 15;
    const float* p0 = Wp + (size_t)(h0 + r0) * H + n0 + c0 * 4;
    const float* p1 = Wp + (size_t)(h0 + r1) * H + n0 + c1 * 4;

    float4 v[2][8];
    #pragma unroll
    for (int j = 0; j < 8; j++) v[0][j] = ldg_v4_nc(p0 + (size_t)j * H * H);
    #pragma unroll
    for (int j = 0; j < 8; j++) v[1][j] = ldg_v4_nc(p1 + (size_t)j * H * H);

    #pragma unroll
    for (int it = 0; it < 2; it++) {
        float4 acc = make_float4(0.f, 0.f, 0.f, 0.f);
        #pragma unroll
        for (int j = 0; j < 8; j++) {
            acc.x += w[j] * v[it][j].x; acc.y += w[j] * v[it][j].y;
            acc.z += w[j] * v[it][j].z; acc.w += w[j] * v[it][j].w;
        }
        int r = it ? r1 : r0, c4 = it ? c1 : c0;
        tile[r][c4 * 4 + 0] = acc.x;
        tile[r][c4 * 4 + 1] = acc.y;
        tile[r][c4 * 4 + 2] = acc.z;
        tile[r][c4 * 4 + 3] = acc.w;
    }
    __syncthreads();
    // transposed store as bf16 pairs: 64 n-rows x 16 h-pairs, 4 iters/thread
    #pragma unroll
    for (int it = 0; it < 4; it++) {
        int i = it * 256 + tid;
        int n = i >> 4, hp = i & 15;
        __nv_bfloat162 pv = __float22bfloat162_rn(
            make_float2(tile[2 * hp][n], tile[2 * hp + 1][n]));
        *(uint32_t*)(g_WeTb + (size_t)(n0 + n) * H + h0 + 2 * hp) = *(uint32_t*)&pv;
    }
}

// ============================================================================
// GEMM1 (bf16): Mtb[n][d] = bf16( sum_h WeTb[n][h] * Wib[d][h] )
//   CTA 64x128, 8 warps of 32x32, m16n8k16, KTILE=64 bf16, 4-stage cp.async.
// ============================================================================
__global__ void __launch_bounds__(256, 1)
k_gemm1(const uint16_t* __restrict__ A, const uint16_t* __restrict__ Bm) {
    constexpr int BM = 64, BN = 128, T = 256;
    constexpr int NKC = 16;
    constexpr int ABYTES = BM * 128;
    constexpr int BBYTES = BN * 128;
    constexpr int STAGE_BYTES = ABYTES + BBYTES;

    extern __shared__ char smem[];
    uint32_t sbase = smem_u32(smem);

    int tid = threadIdx.x;
    int wid = tid >> 5, l = tid & 31;
    int wm = wid % 2, wn = wid / 2;
    int m0 = blockIdx.y * BM;
    int n0 = blockIdx.x * BN;
    int g = l >> 2, c = l & 3;
    int p4 = (g & 1) * 4;

    const uint16_t* gA = A + (size_t)m0 * H;
    const uint16_t* gB = Bm + (size_t)n0 * H;

    auto load_stage = [&](int kc, int stage) {
        uint32_t sA = sbase + stage * STAGE_BYTES;
        uint32_t sB = sA + ABYTES;
        const uint16_t* pA = gA + kc * 64;
        const uint16_t* pB = gB + kc * 64;
        #pragma unroll
        for (int i = tid; i < BM * 8; i += T) {
            int r = i >> 3, ch = i & 7;
            cp16(sA + r * 128 + ((ch ^ ((r & 1) * 4)) << 4), pA + (size_t)r * H + ch * 8);
        }
        #pragma unroll
        for (int i = tid; i < BN * 8; i += T) {
            int r = i >> 3, ch = i & 7;
            cp16(sB + r * 128 + ((ch ^ ((r & 1) * 4)) << 4), pB + (size_t)r * H + ch * 8);
        }
    };

    #pragma unroll
    for (int s = 0; s < STAGES - 1; s++) { load_stage(s, s); CP_COMMIT(); }

    float acc[2][4][4];
    #pragma unroll
    for (int mf = 0; mf < 2; mf++)
        #pragma unroll
        for (int f = 0; f < 4; f++)
            #pragma unroll
            for (int q = 0; q < 4; q++) acc[mf][f][q] = 0.0f;

    int rowA = wm * 32 + g;
    int rowB = wn * 32 + g;

    #pragma unroll 1
    for (int kc0 = 0; kc0 < NKC; kc0 += 4) {
        #pragma unroll
        for (int s4 = 0; s4 < 4; s4++) {
            int kc = kc0 + s4;
            CP_WAIT(STAGES - 2);
            __syncthreads();
            if (kc + STAGES - 1 < NKC) load_stage(kc + STAGES - 1, (kc + STAGES - 1) & 3);
            CP_COMMIT();

            const char* tA = smem + s4 * STAGE_BYTES;
            const char* tB = tA + ABYTES;

            #pragma unroll
            for (int hstep = 0; hstep < 2; hstep++) {
                int ch = (4 * hstep + c) ^ p4;
                uint4 av[4];
                #pragma unroll
                for (int rr = 0; rr < 4; rr++)
                    av[rr] = *(const uint4*)(tA + (rowA + rr * 8) * 128 + ch * 16);
                uint4 bv[4];
                #pragma unroll
                for (int f = 0; f < 4; f++)
                    bv[f] = *(const uint4*)(tB + (rowB + f * 8) * 128 + ch * 16);
                #pragma unroll
                for (int q = 0; q < 2; q++) {
                    #pragma unroll
                    for (int mf = 0; mf < 2; mf++) {
                        uint32_t a[4];
                        if (q == 0) {
                            a[0] = av[2 * mf].x; a[1] = av[2 * mf + 1].x;
                            a[2] = av[2 * mf].y; a[3] = av[2 * mf + 1].y;
                        } else {
                            a[0] = av[2 * mf].z; a[1] = av[2 * mf + 1].z;
                            a[2] = av[2 * mf].w; a[3] = av[2 * mf + 1].w;
                        }
                        #pragma unroll
                        for (int f = 0; f < 4; f++) {
                            uint32_t b[2];
                            if (q == 0) { b[0] = bv[f].x; b[1] = bv[f].y; }
                            else        { b[0] = bv[f].z; b[1] = bv[f].w; }
                            mma_bf16_16(acc[mf][f], a, b);
                        }
                    }
                }
            }
        }
    }

    #pragma unroll
    for (int mf = 0; mf < 2; mf++) {
        #pragma unroll
        for (int hh = 0; hh < 2; hh++) {
            int row = m0 + wm * 32 + mf * 16 + hh * 8 + g;
            #pragma unroll
            for (int f = 0; f < 4; f++) {
                int col = n0 + wn * 32 + f * 8 + 2 * c;
                __nv_bfloat162 pv = __float22bfloat162_rn(
                    make_float2(acc[mf][f][2 * hh], acc[mf][f][2 * hh + 1]));
                *(uint32_t*)(g_Mtb + (size_t)row * H + col) = *(uint32_t*)&pv;
            }
        }
    }
}

// ============================================================================
// GEMM2 (bf16 + fused coh): acc = xb@Mtb^T + sum_j w[j]*coh ; out = c1*acc
//   CTA 128x128, 16 warps of 32x32, m16n8k16, KTILE=64 bf16, 4-stage cp.async.
//   Per ktile kc: j=kc>>1, mf=kc&1 -> 8 __ldcs float2 of coh + 16 FFMA into acc.
// ============================================================================
__global__ void __launch_bounds__(512, 1)
k_gemm2(const uint16_t* __restrict__ A, const uint16_t* __restrict__ Bm,
        float* __restrict__ out, const float* __restrict__ coh) {
    constexpr int BM = 128, BN = 128, T = 512;
    constexpr int NKC = 16;
    constexpr int ABYTES = BM * 128;
    constexpr int BBYTES = BN * 128;
    constexpr int STAGE_BYTES = ABYTES + BBYTES;

    extern __shared__ char smem[];
    uint32_t sbase = smem_u32(smem);

    int tid = threadIdx.x;
    int wid = tid >> 5, l = tid & 31;
    int wm = wid % 4, wn = wid / 4;
    int m0 = blockIdx.y * BM;
    int n0 = blockIdx.x * BN;
    int g = l >> 2, c = l & 3;
    int p4 = (g & 1) * 4;

    const uint16_t* gA = A + (size_t)m0 * H;
    const uint16_t* gB = Bm + (size_t)n0 * H;

    float w[8];
    #pragma unroll
    for (int j = 0; j < 8; j++) w[j] = g_w[j];

    const float* cohbase = coh + n0 + wn * 32 + 2 * c;

    auto load_stage = [&](int kc, int stage) {
        uint32_t sA = sbase + stage * STAGE_BYTES;
        uint32_t sB = sA + ABYTES;
        const uint16_t* pA = gA + kc * 64;
        const uint16_t* pB = gB + kc * 64;
        #pragma unroll
        for (int i = tid; i < BM * 8; i += T) {
            int r = i >> 3, ch = i & 7;
            cp16(sA + r * 128 + ((ch ^ ((r & 1) * 4)) << 4), pA + (size_t)r * H + ch * 8);
        }
        #pragma unroll
        for (int i = tid; i < BN * 8; i += T) {
            int r = i >> 3, ch = i & 7;
            cp16(sB + r * 128 + ((ch ^ ((r & 1) * 4)) << 4), pB + (size_t)r * H + ch * 8);
        }
    };

    #pragma unroll
    for (int s = 0; s < STAGES - 1; s++) { load_stage(s, s); CP_COMMIT(); }

    float acc[2][4][4];
    #pragma unroll
    for (int mf = 0; mf < 2; mf++)
        #pragma unroll
        for (int f = 0; f < 4; f++)
            #pragma unroll
            for (int q = 0; q < 4; q++) acc[mf][f][q] = 0.0f;

    int rowA = wm * 32 + g;
    int rowB = wn * 32 + g;

    #pragma unroll 1
    for (int kc0 = 0; kc0 < NKC; kc0 += 4) {
        #pragma unroll
        for (int s4 = 0; s4 < 4; s4++) {
            int kc = kc0 + s4;
            CP_WAIT(STAGES - 2);
            __syncthreads();
            if (kc + STAGES - 1 < NKC) load_stage(kc + STAGES - 1, (kc + STAGES - 1) & 3);
            CP_COMMIT();

            // ---- coh loads for (j = kc>>1, mf = kc&1) ----
            int j = kc >> 1;
            int mfc = kc & 1;
            float2 ct[2][4];
            {
                #pragma unroll
                for (int hh = 0; hh < 2; hh++) {
                    int row = m0 + wm * 32 + mfc * 16 + hh * 8 + g;
                    const float* cp = cohbase + ((size_t)row * 8 + j) * H;
                    #pragma unroll
                    for (int f = 0; f < 4; f++)
                        ct[hh][f] = __ldcs((const float2*)(cp + f * 8));
                }
            }

            const char* tA = smem + s4 * STAGE_BYTES;
            const char* tB = tA + ABYTES;

            #pragma unroll
            for (int hstep = 0; hstep < 2; hstep++) {
                int ch = (4 * hstep + c) ^ p4;
                uint4 av[4];
                #pragma unroll
                for (int rr = 0; rr < 4; rr++)
                    av[rr] = *(const uint4*)(tA + (rowA + rr * 8) * 128 + ch * 16);
                uint4 bv[4];
                #pragma unroll
                for (int f = 0; f < 4; f++)
                    bv[f] = *(const uint4*)(tB + (rowB + f * 8) * 128 + ch * 16);
                #pragma unroll
                for (int q = 0; q < 2; q++) {
                    #pragma unroll
                    for (int mf = 0; mf < 2; mf++) {
                        uint32_t a[4];
                        if (q == 0) {
                            a[0] = av[2 * mf].x; a[1] = av[2 * mf + 1].x;
                            a[2] = av[2 * mf].y; a[3] = av[2 * mf + 1].y;
                        } else {
                            a[0] = av[2 * mf].z; a[1] = av[2 * mf + 1].z;
                            a[2] = av[2 * mf].w; a[3] = av[2 * mf + 1].w;
                        }
                        #pragma unroll
                        for (int f = 0; f < 4; f++) {
                            uint32_t b[2];
                            if (q == 0) { b[0] = bv[f].x; b[1] = bv[f].y; }
                            else        { b[0] = bv[f].z; b[1] = bv[f].w; }
                            mma_bf16_16(acc[mf][f], a, b);
                        }
                    }
                }
            }

            // ---- apply coh FMAs into acc ----
            float wj = w[j];
            #pragma unroll
            for (int hh = 0; hh < 2; hh++) {
                #pragma unroll
                for (int f = 0; f < 4; f++) {
                    acc[mfc][f][2 * hh]     += wj * ct[hh][f].x;
                    acc[mfc][f][2 * hh + 1] += wj * ct[hh][f].y;
                }
            }
        }
    }

    // ----------------- epilogue: out = c1 * acc -----------------
    float c1 = g_c[0];
    #pragma unroll
    for (int mf = 0; mf < 2; mf++) {
        #pragma unroll
        for (int hh = 0; hh < 2; hh++) {
            int row = m0 + wm * 32 + mf * 16 + hh * 8 + g;
            #pragma unroll
            for (int f = 0; f < 4; f++) {
                int col = n0 + wn * 32 + f * 8 + 2 * c;
                *(float2*)(out + (size_t)row * H + col) =
                    make_float2(c1 * acc[mf][f][2 * hh], c1 * acc[mf][f][2 * hh + 1]);
            }
        }
    }
}

// ============================================================================
// Host side
// ============================================================================
extern "C" void kernel_launch(void* const* d_in, const int* in_sizes, int n_in,
                              void* d_out, int out_size) {
    const float* x   = (const float*)d_in[0];   // [2048, 1024]
    const float* Wi  = (const float*)d_in[1];   // [1024, 1024]
    const float* Wp  = (const float*)d_in[2];   // [8, 1024, 1024]
    const float* J   = (const float*)d_in[3];   // [8, 8]
    const float* coh = (const float*)d_in[4];   // [2048, 8, 1024]
    const float* t   = (const float*)d_in[5];   // [1]
    float* out = (float*)d_out;                 // [2048, 1024]
    (void)in_sizes; (void)n_in; (void)out_size;

    void* wetb_ptr = nullptr;
    void* wib_ptr = nullptr;
    void* mtb_ptr = nullptr;
    void* xb_ptr = nullptr;
    cudaGetSymbolAddress(&wetb_ptr, g_WeTb);
    cudaGetSymbolAddress(&wib_ptr, g_Wib);
    cudaGetSymbolAddress(&mtb_ptr, g_Mtb);
    cudaGetSymbolAddress(&xb_ptr, g_xb);

    constexpr int SMEM1 = STAGES * (64 * 128 + 128 * 128);    // 96 KB
    constexpr int SMEM2 = STAGES * (128 * 128 + 128 * 128);   // 128 KB
    cudaFuncSetAttribute((const void*)k_gemm1,
                         cudaFuncAttributeMaxDynamicSharedMemorySize, SMEM1);
    cudaFuncSetAttribute((const void*)k_gemm2,
                         cudaFuncAttributeMaxDynamicSharedMemorySize, SMEM2);

    k_scalars<<<1, 64>>>(J, t);
    k_conv<<<NXB + NWB, 256>>>(x, Wi);          // xb (needs g_c[2]) + Wib
    k_wet<<<dim3(32, 16), 256>>>(Wp);
    // GEMM1: Mtb[n][d] = bf16( sum_h WeTb[n][h] * Wib[d][h] )
    k_gemm1<<<dim3(8, 16), 256, SMEM1>>>(
        (const uint16_t*)wetb_ptr, (const uint16_t*)wib_ptr);
    // GEMM2: acc = xb@Mtb^T + sum_j w[j]*coh ; out = c1*acc
    k_gemm2<<<dim3(8, 16), 512, SMEM2>>>(
        (const uint16_t*)xb_ptr, (const uint16_t*)mtb_ptr, out, coh);
}